// round 3
// baseline (speedup 1.0000x reference)
#include <cuda_runtime.h>
#include <cuda_bf16.h>
#include <cstdint>
#include <cstddef>

#define NN 16384
#define HH 256
#define DIN 512
#define SS 8
#define MAXNZ 64
#define NH 4194304UL  // NN*HH floats

// exp(x/tau) = exp2(x * log2(e)/tau), tau = 0.5
#define EXPC 2.8853900817779268f
// exp(1/tau) = exp(2)
#define EDIAG 7.389056098930650f

// ---------------------------------------------------------------------------
// Scratch: one big __device__ global, carved by compile-time offsets.
// ---------------------------------------------------------------------------
__device__ float g_scratch[19 * NH + 2 * (NN * MAXNZ) + 2 * NN + 8 * NN];

// float-offset layout
#define O_P1   (0 * NH)
#define O_P2   (1 * NH)
#define O_T1   (2 * NH)
#define O_H1   (3 * NH)
#define O_H2   (4 * NH)
#define O_G3A  (5 * NH)
#define O_G3B  (6 * NH)
#define O_H3   (7 * NH)
#define O_UA   (8 * NH)
#define O_UB   (9 * NH)
#define O_U    (10 * NH)
#define O_T0   (11 * NH)
#define O_TT1  (12 * NH)
#define O_PROJ (13 * NH)
#define O_H1P  (14 * NH)
#define O_H2P  (15 * NH)
#define O_VN   (16 * NH)
#define O_UEMD (17 * NH)
#define O_Z1   (18 * NH)  // bf16 region: Z1 (NH bf16) then Z2 (NH bf16)
#define O_TAIL (19 * NH)
#define O_COLS1 (O_TAIL)
#define O_COLS2 (O_COLS1 + (size_t)NN * MAXNZ)
#define O_CNT1  (O_COLS2 + (size_t)NN * MAXNZ)
#define O_CNT2  (O_CNT1 + NN)
#define O_R1    (O_CNT2 + NN)
#define O_R2    (O_R1 + NN)
#define O_BR    (O_R2 + NN)
#define O_BC    (O_BR + NN)
#define O_SII   (O_BC + NN)
#define O_LSEM  (O_SII + NN)
#define O_LG    (O_LSEM + NN)

__device__ __forceinline__ float* scr(size_t off) { return g_scratch + off; }
__device__ __forceinline__ int* scri(size_t off) { return (int*)(g_scratch + off); }

// ---------------------------------------------------------------------------

__global__ void k_zero4() {
    int i = blockIdx.x * blockDim.x + threadIdx.x;
    if (i < NN) {
        scr(O_R1)[i] = 0.f; scr(O_R2)[i] = 0.f;
        scr(O_BR)[i] = 0.f; scr(O_BC)[i] = 0.f;
    }
}

// Extract sparse structure of one adjacency row per block.
__global__ void k_extract(const float* __restrict__ adj, size_t colsOff, size_t cntOff) {
    int* cols = scri(colsOff);
    int* cnts = scri(cntOff);
    int row = blockIdx.x;
    __shared__ int scnt;
    if (threadIdx.x == 0) scnt = 0;
    __syncthreads();
    const float4* a4 = (const float4*)(adj + (size_t)row * NN);
    for (int i = threadIdx.x; i < NN / 4; i += blockDim.x) {
        float4 v = a4[i];
        int base = i * 4;
        if (v.x != 0.f) { int s = atomicAdd(&scnt, 1); if (s < MAXNZ) cols[(size_t)row * MAXNZ + s] = base + 0; }
        if (v.y != 0.f) { int s = atomicAdd(&scnt, 1); if (s < MAXNZ) cols[(size_t)row * MAXNZ + s] = base + 1; }
        if (v.z != 0.f) { int s = atomicAdd(&scnt, 1); if (s < MAXNZ) cols[(size_t)row * MAXNZ + s] = base + 2; }
        if (v.w != 0.f) { int s = atomicAdd(&scnt, 1); if (s < MAXNZ) cols[(size_t)row * MAXNZ + s] = base + 3; }
    }
    __syncthreads();
    if (threadIdx.x == 0) cnts[row] = scnt > MAXNZ ? MAXNZ : scnt;
}

// Row-normalized SpMM: out[r,:] = (1/cnt) * sum_j X[cols[j],:] + bias
__global__ void k_spmm(size_t colsOff, size_t cntOff, size_t XOff,
                       const float* __restrict__ bias, size_t outOff) {
    const int* cols = scri(colsOff);
    const float* X = scr(XOff);
    float* out = scr(outOff);
    __shared__ int sc[MAXNZ];
    int row = blockIdx.x;
    int cnt = scri(cntOff)[row];
    if (threadIdx.x < cnt) sc[threadIdx.x] = cols[(size_t)row * MAXNZ + threadIdx.x];
    __syncthreads();
    float acc = 0.f;
    for (int j = 0; j < cnt; j++) acc += X[(size_t)sc[j] * HH + threadIdx.x];
    float v = cnt > 0 ? (1.0f / (float)cnt) : 0.0f;
    out[(size_t)row * HH + threadIdx.x] = v * acc + bias[threadIdx.x];
}

// fp32 SGEMM: C[NN,256] = A[NN,K] @ B[K,256] (+bias)(+relu)
__global__ __launch_bounds__(256) void k_gemm(const float* Aext, size_t AOff,
                                              const float* __restrict__ B,
                                              const float* __restrict__ bias,
                                              size_t COff, int K, int relu) {
    const float* __restrict__ A = Aext ? Aext : scr(AOff);
    float* C = scr(COff);
    __shared__ float As[16][132];
    __shared__ float Bs[16][132];
    int bn = blockIdx.x * 128;
    int bm = blockIdx.y * 128;
    int tid = threadIdx.x;
    int tx = tid & 15, ty = tid >> 4;
    float acc[8][8];
#pragma unroll
    for (int i = 0; i < 8; i++)
#pragma unroll
        for (int j = 0; j < 8; j++) acc[i][j] = 0.f;

    for (int k0 = 0; k0 < K; k0 += 16) {
#pragma unroll
        for (int t = 0; t < 2; t++) {
            int idx = tid + 256 * t;
            int r = idx >> 2; int kq = (idx & 3) * 4;
            float4 v = *(const float4*)(A + (size_t)(bm + r) * K + k0 + kq);
            As[kq + 0][r] = v.x; As[kq + 1][r] = v.y; As[kq + 2][r] = v.z; As[kq + 3][r] = v.w;
            int kb = idx >> 5; int nq = (idx & 31) * 4;
            float4 w = *(const float4*)(B + (size_t)(k0 + kb) * HH + bn + nq);
            *(float4*)&Bs[kb][nq] = w;
        }
        __syncthreads();
#pragma unroll
        for (int k = 0; k < 16; k++) {
            float a[8], b[8];
            *(float4*)(a)     = *(const float4*)&As[k][ty * 8];
            *(float4*)(a + 4) = *(const float4*)&As[k][ty * 8 + 4];
            *(float4*)(b)     = *(const float4*)&Bs[k][tx * 8];
            *(float4*)(b + 4) = *(const float4*)&Bs[k][tx * 8 + 4];
#pragma unroll
            for (int i = 0; i < 8; i++)
#pragma unroll
                for (int j = 0; j < 8; j++) acc[i][j] += a[i] * b[j];
        }
        __syncthreads();
    }
#pragma unroll
    for (int i = 0; i < 8; i++) {
        int row = bm + ty * 8 + i;
#pragma unroll
        for (int j = 0; j < 8; j++) {
            int col = bn + tx * 8 + j;
            float v = acc[i][j] + (bias ? bias[col] : 0.f);
            if (relu) v = fmaxf(v, 0.f);
            C[(size_t)row * HH + col] = v;
        }
    }
}

// Row l2-normalize; optionally emit bf16 copy at bOff (bf16 element offset).
__global__ void k_l2norm(size_t XOff, size_t outOff, int emitB, size_t bOff) {
    const float* X = scr(XOff);
    float* out = scr(outOff);
    int row = blockIdx.x, t = threadIdx.x;
    float x = X[(size_t)row * HH + t];
    float s = x * x;
#pragma unroll
    for (int o = 16; o; o >>= 1) s += __shfl_xor_sync(0xffffffffu, s, o);
    __shared__ float red[8];
    if ((t & 31) == 0) red[t >> 5] = s;
    __syncthreads();
    float tot = 0.f;
#pragma unroll
    for (int i = 0; i < 8; i++) tot += red[i];
    float inv = 1.0f / fmaxf(sqrtf(tot), 1e-12f);
    float y = x * inv;
    out[(size_t)row * HH + t] = y;
    if (emitB) {
        __nv_bfloat16* ob = (__nv_bfloat16*)scr(O_Z1) + bOff;
        ob[(size_t)row * HH + t] = __float2bfloat16(y);
    }
}

__device__ __forceinline__ void mma16816v(float c[4], const uint32_t a[4], const uint32_t b[2]) {
    asm volatile(
        "mma.sync.aligned.m16n8k16.row.col.f32.bf16.bf16.f32 "
        "{%0,%1,%2,%3}, {%4,%5,%6,%7}, {%8,%9}, {%0,%1,%2,%3};\n"
        : "+f"(c[0]), "+f"(c[1]), "+f"(c[2]), "+f"(c[3])
        : "r"(a[0]), "r"(a[1]), "r"(a[2]), "r"(a[3]), "r"(b[0]), "r"(b[1]));
}

// Fused gram: S = A @ B^T (bf16 mma, fp32 accum), exp(S/tau), row/col sums.
__global__ __launch_bounds__(256) void k_gram(size_t AOff, size_t BOff,
                                              size_t rowOff, long long colOff,
                                              int symmetric) {
    int bx = blockIdx.x, by = blockIdx.y;
    if (symmetric && bx < by) return;
    const __nv_bfloat16* A = (const __nv_bfloat16*)scr(O_Z1) + AOff;
    const __nv_bfloat16* Bm = (const __nv_bfloat16*)scr(O_Z1) + BOff;
    float* rowSum = scr(rowOff);
    __shared__ __nv_bfloat16 As[128][40];
    __shared__ __nv_bfloat16 Bs[128][40];
    int tid = threadIdx.x;
    int wid = tid >> 5, lane = tid & 31;
    int warpM = wid >> 2, warpN = wid & 3;
    int g = lane >> 2, tig = lane & 3;
    const int rowBase = by * 128, colBase = bx * 128;

    float acc[4][4][4];
#pragma unroll
    for (int a = 0; a < 4; a++)
#pragma unroll
        for (int b = 0; b < 4; b++)
#pragma unroll
            for (int q = 0; q < 4; q++) acc[a][b][q] = 0.f;

    for (int k0 = 0; k0 < HH; k0 += 32) {
#pragma unroll
        for (int t = 0; t < 2; t++) {
            int idx = tid + t * 256;
            int r = idx >> 2, kq = (idx & 3);
            *(uint4*)(&As[r][kq * 8]) = *(const uint4*)(A + (size_t)(rowBase + r) * HH + k0 + kq * 8);
            *(uint4*)(&Bs[r][kq * 8]) = *(const uint4*)(Bm + (size_t)(colBase + r) * HH + k0 + kq * 8);
        }
        __syncthreads();
#pragma unroll
        for (int kk = 0; kk < 32; kk += 16) {
            uint32_t af[4][4], bf[4][2];
#pragma unroll
            for (int mt = 0; mt < 4; mt++) {
                int r0 = warpM * 64 + mt * 16 + g;
                af[mt][0] = *(const uint32_t*)&As[r0][kk + tig * 2];
                af[mt][1] = *(const uint32_t*)&As[r0 + 8][kk + tig * 2];
                af[mt][2] = *(const uint32_t*)&As[r0][kk + tig * 2 + 8];
                af[mt][3] = *(const uint32_t*)&As[r0 + 8][kk + tig * 2 + 8];
            }
#pragma unroll
            for (int nt = 0; nt < 4; nt++) {
                int c0 = warpN * 32 + nt * 8 + g;
                bf[nt][0] = *(const uint32_t*)&Bs[c0][kk + tig * 2];
                bf[nt][1] = *(const uint32_t*)&Bs[c0][kk + tig * 2 + 8];
            }
#pragma unroll
            for (int mt = 0; mt < 4; mt++)
#pragma unroll
                for (int nt = 0; nt < 4; nt++) mma16816v(acc[mt][nt], af[mt], bf[nt]);
        }
        __syncthreads();
    }

    float rs[4][2], cs[4][2];
#pragma unroll
    for (int i = 0; i < 4; i++) { rs[i][0] = rs[i][1] = 0.f; cs[i][0] = cs[i][1] = 0.f; }
#pragma unroll
    for (int mt = 0; mt < 4; mt++)
#pragma unroll
        for (int nt = 0; nt < 4; nt++) {
            float e0 = exp2f(acc[mt][nt][0] * EXPC);
            float e1 = exp2f(acc[mt][nt][1] * EXPC);
            float e2 = exp2f(acc[mt][nt][2] * EXPC);
            float e3 = exp2f(acc[mt][nt][3] * EXPC);
            rs[mt][0] += e0 + e1; rs[mt][1] += e2 + e3;
            cs[nt][0] += e0 + e2; cs[nt][1] += e1 + e3;
        }
#pragma unroll
    for (int mt = 0; mt < 4; mt++)
#pragma unroll
        for (int h = 0; h < 2; h++) {
            float v = rs[mt][h];
            v += __shfl_xor_sync(0xffffffffu, v, 1);
            v += __shfl_xor_sync(0xffffffffu, v, 2);
            if (tig == 0) {
                int r = rowBase + warpM * 64 + mt * 16 + g + h * 8;
                atomicAdd(&rowSum[r], v);
            }
        }
    bool wantCol = symmetric ? (bx != by) : (colOff >= 0);
    if (wantCol) {
        float* dst = symmetric ? rowSum : scr((size_t)colOff);
#pragma unroll
        for (int nt = 0; nt < 4; nt++)
#pragma unroll
            for (int h = 0; h < 2; h++) {
                float v = cs[nt][h];
                v += __shfl_xor_sync(0xffffffffu, v, 4);
                v += __shfl_xor_sync(0xffffffffu, v, 8);
                v += __shfl_xor_sync(0xffffffffu, v, 16);
                if (g == 0) {
                    int c = colBase + warpN * 32 + nt * 8 + tig * 2 + h;
                    atomicAdd(&dst[c], v);
                }
            }
    }
}

// sii[i] = dot(A_i, B_i) in fp32 (exact diagonal of "between")
__global__ void k_sii(size_t AOff, size_t BOff, size_t sOff) {
    const float* A = scr(AOff);
    const float* B = scr(BOff);
    int w = threadIdx.x >> 5, lane = threadIdx.x & 31;
    int row = blockIdx.x * 8 + w;
    const float* a = A + (size_t)row * HH + lane * 8;
    const float* b = B + (size_t)row * HH + lane * 8;
    float4 a0 = *(const float4*)a, a1 = *(const float4*)(a + 4);
    float4 b0 = *(const float4*)b, b1 = *(const float4*)(b + 4);
    float s = a0.x * b0.x + a0.y * b0.y + a0.z * b0.z + a0.w * b0.w +
              a1.x * b1.x + a1.y * b1.y + a1.z * b1.z + a1.w * b1.w;
#pragma unroll
    for (int o = 16; o; o >>= 1) s += __shfl_xor_sync(0xffffffffu, s, o);
    if (lane == 0) scr(sOff)[row] = s;
}

__global__ void k_semi() {
    int i = blockIdx.x * blockDim.x + threadIdx.x;
    if (i >= NN) return;
    float dl = scr(O_SII)[i] * 2.0f;  // log(diag) = dot/tau
    float l1 = logf(scr(O_R1)[i] + scr(O_BR)[i] - EDIAG) - dl;
    float l2 = logf(scr(O_R2)[i] + scr(O_BC)[i] - EDIAG) - dl;
    scr(O_LSEM)[i] = 0.5f * (l1 + l2);
}

__global__ void k_contrast(const int* __restrict__ nbi, const int* __restrict__ ngi) {
    const float* proj = scr(O_PROJ);
    const float* uemd = scr(O_UEMD);
    const float* vn = scr(O_VN);
    int w = threadIdx.x >> 5, lane = threadIdx.x & 31;
    int n = blockIdx.x * 8 + w;
    float p[8], v[8];
    {
        const float4* pp = (const float4*)(proj + (size_t)n * HH + lane * 8);
        ((float4*)p)[0] = pp[0]; ((float4*)p)[1] = pp[1];
        const float4* vv = (const float4*)(vn + (size_t)n * HH + lane * 8);
        ((float4*)v)[0] = vv[0]; ((float4*)v)[1] = vv[1];
    }
    float posd[SS];
    float negsum = 0.f;
#pragma unroll
    for (int s = 0; s < SS; s++) {
        int nb = nbi[n * SS + s];
        const float4* uu = (const float4*)(uemd + (size_t)nb * HH + lane * 8);
        float u[8]; ((float4*)u)[0] = uu[0]; ((float4*)u)[1] = uu[1];
        float d = 0.f;
#pragma unroll
        for (int k = 0; k < 8; k++) d += p[k] * u[k];
#pragma unroll
        for (int o = 16; o; o >>= 1) d += __shfl_xor_sync(0xffffffffu, d, o);
        posd[s] = d;
        int ng = ngi[n * SS + s];
        const float4* qq = (const float4*)(vn + (size_t)ng * HH + lane * 8);
        float q[8]; ((float4*)q)[0] = qq[0]; ((float4*)q)[1] = qq[1];
        float d2 = 0.f;
#pragma unroll
        for (int k = 0; k < 8; k++) d2 += v[k] * q[k];
#pragma unroll
        for (int o = 16; o; o >>= 1) d2 += __shfl_xor_sync(0xffffffffu, d2, o);
        negsum += exp2f(d2 * EXPC);
    }
    float ns = 0.f, ps = 0.f;
#pragma unroll
    for (int s = 0; s < SS; s++) {
        float pos = exp2f(posd[s] * EXPC);
        ns += logf(pos + negsum);
        ps += posd[s] * 2.0f;  // log(pos) = dot/tau
    }
    if (lane == 0) scr(O_LG)[n] = ns - ps;  // LAMBDA = 1
}

// Deterministic single-block reduction + scalar finalize.
__global__ void k_reduce(float* __restrict__ out) {
    __shared__ float s1[1024], s2[1024];
    int t = threadIdx.x;
    float a = 0.f, b = 0.f;
    for (int i = t; i < NN; i += 1024) { a += scr(O_LG)[i]; b += scr(O_LSEM)[i]; }
    s1[t] = a; s2[t] = b;
    __syncthreads();
    for (int s = 512; s > 0; s >>= 1) {
        if (t < s) { s1[t] += s1[t + s]; s2[t] += s2[t + s]; }
        __syncthreads();
    }
    if (t == 0) {
        float gacl = s1[0] / ((float)NN * (float)SS);
        float sem = s2[0] / (float)NN;
        out[0] = gacl + 0.6f * sem;
        out[1] = gacl;
        out[2] = sem;
    }
}

// Alignment-agnostic copy: vector loads from aligned scratch, scalar stores
// (dst = out + 3 is NOT 16B aligned).
__global__ void k_copy(size_t srcOff, float* __restrict__ dst, size_t n4) {
    size_t i = (size_t)blockIdx.x * blockDim.x + threadIdx.x;
    if (i < n4) {
        float4 v = ((const float4*)scr(srcOff))[i];
        float* d = dst + i * 4;
        d[0] = v.x; d[1] = v.y; d[2] = v.z; d[3] = v.w;
    }
}

// ---------------------------------------------------------------------------
// Host launch — kernel launches ONLY.
// ---------------------------------------------------------------------------
extern "C" void kernel_launch(void* const* d_in, const int* in_sizes, int n_in,
                              void* d_out, int out_size) {
    const float* adj1 = (const float*)d_in[0];
    const float* adj2 = (const float*)d_in[1];
    const float* x1 = (const float*)d_in[2];
    const float* x2 = (const float*)d_in[3];
    const int* nbi = (const int*)d_in[4];
    const int* ngi = (const int*)d_in[5];
    const float* W1 = (const float*)d_in[6];
    const float* b1 = (const float*)d_in[7];
    const float* W2 = (const float*)d_in[8];
    const float* b2 = (const float*)d_in[9];
    const float* tW1 = (const float*)d_in[10];
    const float* tb1 = (const float*)d_in[11];
    const float* tW2 = (const float*)d_in[12];
    const float* tb2 = (const float*)d_in[13];
    const float* pW0 = (const float*)d_in[14];
    const float* pB0 = (const float*)d_in[15];
    const float* pW1 = (const float*)d_in[16];
    const float* pB1 = (const float*)d_in[17];
    const float* pW2 = (const float*)d_in[18];
    const float* pB2 = (const float*)d_in[19];
    const float* sW0 = (const float*)d_in[20];
    const float* sB0 = (const float*)d_in[21];
    const float* sW1 = (const float*)d_in[22];
    const float* sB1 = (const float*)d_in[23];
    const float* sW2 = (const float*)d_in[24];
    const float* sB2 = (const float*)d_in[25];

    float* out = (float*)d_out;
    size_t h3_off = (size_t)out_size - NH;  // scalars precede h3

    dim3 gemmGrid(2, NN / 128);
    dim3 gramGrid(128, 128);

    k_zero4<<<NN / 256, 256>>>();
    k_extract<<<NN, 256>>>(adj1, O_COLS1, O_CNT1);
    k_extract<<<NN, 256>>>(adj2, O_COLS2, O_CNT2);

    // stage A: X @ W (bias deferred to spmm)
    k_gemm<<<gemmGrid, 256>>>(x1, 0, W1, nullptr, O_P1, DIN, 0);
    k_gemm<<<gemmGrid, 256>>>(x2, 0, W1, nullptr, O_P2, DIN, 0);
    k_gemm<<<gemmGrid, 256>>>(x1, 0, tW1, nullptr, O_T1, DIN, 0);

    // graph convs (sparse)
    k_spmm<<<NN, 256>>>(O_COLS1, O_CNT1, O_P1, b1, O_H1);
    k_spmm<<<NN, 256>>>(O_COLS1, O_CNT1, O_P2, b1, O_H2);
    k_spmm<<<NN, 256>>>(O_COLS2, O_CNT2, O_P1, b1, O_G3A);
    k_spmm<<<NN, 256>>>(O_COLS2, O_CNT2, O_T1, tb1, O_UA);

    k_gemm<<<gemmGrid, 256>>>(nullptr, O_G3A, W2, nullptr, O_G3B, HH, 0);
    k_gemm<<<gemmGrid, 256>>>(nullptr, O_UA, tW2, nullptr, O_UB, HH, 0);

    k_spmm<<<NN, 256>>>(O_COLS2, O_CNT2, O_G3B, b2, O_H3);
    k_spmm<<<NN, 256>>>(O_COLS2, O_CNT2, O_UB, tb2, O_U);

    k_l2norm<<<NN, 256>>>(O_U, O_UEMD, 0, 0);
    k_l2norm<<<NN, 256>>>(O_H3, O_VN, 0, 0);

    // projection MLP on h3
    k_gemm<<<gemmGrid, 256>>>(nullptr, O_H3, pW0, pB0, O_T0, HH, 1);
    k_gemm<<<gemmGrid, 256>>>(nullptr, O_T0, pW1, pB1, O_TT1, HH, 1);
    k_gemm<<<gemmGrid, 256>>>(nullptr, O_TT1, pW2, pB2, O_T0, HH, 0);
    k_l2norm<<<NN, 256>>>(O_T0, O_PROJ, 0, 0);

    // semantic MLP on h1 -> h1p (+bf16 Z1)
    k_gemm<<<gemmGrid, 256>>>(nullptr, O_H1, sW0, sB0, O_T0, HH, 1);
    k_gemm<<<gemmGrid, 256>>>(nullptr, O_T0, sW1, sB1, O_TT1, HH, 1);
    k_gemm<<<gemmGrid, 256>>>(nullptr, O_TT1, sW2, sB2, O_T0, HH, 0);
    k_l2norm<<<NN, 256>>>(O_T0, O_H1P, 1, 0);

    // semantic MLP on h2 -> h2p (+bf16 Z2)
    k_gemm<<<gemmGrid, 256>>>(nullptr, O_H2, sW0, sB0, O_T0, HH, 1);
    k_gemm<<<gemmGrid, 256>>>(nullptr, O_T0, sW1, sB1, O_TT1, HH, 1);
    k_gemm<<<gemmGrid, 256>>>(nullptr, O_TT1, sW2, sB2, O_T0, HH, 0);
    k_l2norm<<<NN, 256>>>(O_T0, O_H2P, 1, NH);

    // fused exp-gram row/col sums
    k_gram<<<gramGrid, 256>>>(0, 0, O_R1, -1, 1);
    k_gram<<<gramGrid, 256>>>(NH, NH, O_R2, -1, 1);
    k_gram<<<gramGrid, 256>>>(0, NH, O_BR, (long long)O_BC, 0);

    k_sii<<<NN / 8, 256>>>(O_H1P, O_H2P, O_SII);
    k_semi<<<NN / 256, 256>>>();
    k_contrast<<<NN / 8, 256>>>(nbi, ngi);

    k_reduce<<<1, 1024>>>(out);
    k_copy<<<(unsigned)((NH / 4 + 255) / 256), 256>>>(O_H3, out + h3_off, NH / 4);
}

// round 4
// speedup vs baseline: 1.3122x; 1.3122x over previous
#include <cuda_runtime.h>
#include <cuda_bf16.h>
#include <cstdint>
#include <cstddef>

#define NN 16384
#define HH 256
#define DIN 512
#define SS 8
#define MAXNZ 64
#define NH 4194304UL  // NN*HH floats

// exp(x/tau) = exp2(x * log2(e)/tau), tau = 0.5
#define EXPC 2.8853900817779268f
// exp(1/tau) = exp(2)
#define EDIAG 7.389056098930650f

// ---------------------------------------------------------------------------
// Scratch: one big __device__ global, carved by compile-time offsets.
// ---------------------------------------------------------------------------
__device__ float g_scratch[19 * NH + 2 * (NN * MAXNZ) + 2 * NN + 8 * NN];

// float-offset layout
#define O_P1   (0 * NH)
#define O_P2   (1 * NH)
#define O_T1   (2 * NH)
#define O_H1   (3 * NH)
#define O_H2   (4 * NH)
#define O_G3A  (5 * NH)
#define O_G3B  (6 * NH)
#define O_H3   (7 * NH)
#define O_UA   (8 * NH)
#define O_UB   (9 * NH)
#define O_U    (10 * NH)
#define O_T0   (11 * NH)
#define O_TT1  (12 * NH)
#define O_PROJ (13 * NH)
#define O_H1P  (14 * NH)
#define O_H2P  (15 * NH)
#define O_VN   (16 * NH)
#define O_UEMD (17 * NH)
#define O_Z1   (18 * NH)  // bf16 region: Z1 (NH bf16) then Z2 (NH bf16)
#define O_TAIL (19 * NH)
#define O_COLS1 (O_TAIL)
#define O_COLS2 (O_COLS1 + (size_t)NN * MAXNZ)
#define O_CNT1  (O_COLS2 + (size_t)NN * MAXNZ)
#define O_CNT2  (O_CNT1 + NN)
#define O_R1    (O_CNT2 + NN)
#define O_R2    (O_R1 + NN)
#define O_BR    (O_R2 + NN)
#define O_BC    (O_BR + NN)
#define O_SII   (O_BC + NN)
#define O_LSEM  (O_SII + NN)
#define O_LG    (O_LSEM + NN)

__device__ __forceinline__ float* scr(size_t off) { return g_scratch + off; }
__device__ __forceinline__ int* scri(size_t off) { return (int*)(g_scratch + off); }

// ---------------------------------------------------------------------------

__global__ void k_zero4() {
    int i = blockIdx.x * blockDim.x + threadIdx.x;
    if (i < NN) {
        scr(O_R1)[i] = 0.f; scr(O_R2)[i] = 0.f;
        scr(O_BR)[i] = 0.f; scr(O_BC)[i] = 0.f;
    }
}

// Extract sparse structure of one adjacency row per block.
__global__ void k_extract(const float* __restrict__ adj, size_t colsOff, size_t cntOff) {
    int* cols = scri(colsOff);
    int* cnts = scri(cntOff);
    int row = blockIdx.x;
    __shared__ int scnt;
    if (threadIdx.x == 0) scnt = 0;
    __syncthreads();
    const float4* a4 = (const float4*)(adj + (size_t)row * NN);
    for (int i = threadIdx.x; i < NN / 4; i += blockDim.x) {
        float4 v = a4[i];
        int base = i * 4;
        if (v.x != 0.f) { int s = atomicAdd(&scnt, 1); if (s < MAXNZ) cols[(size_t)row * MAXNZ + s] = base + 0; }
        if (v.y != 0.f) { int s = atomicAdd(&scnt, 1); if (s < MAXNZ) cols[(size_t)row * MAXNZ + s] = base + 1; }
        if (v.z != 0.f) { int s = atomicAdd(&scnt, 1); if (s < MAXNZ) cols[(size_t)row * MAXNZ + s] = base + 2; }
        if (v.w != 0.f) { int s = atomicAdd(&scnt, 1); if (s < MAXNZ) cols[(size_t)row * MAXNZ + s] = base + 3; }
    }
    __syncthreads();
    if (threadIdx.x == 0) cnts[row] = scnt > MAXNZ ? MAXNZ : scnt;
}

// Row-normalized SpMM: out[r,:] = (1/cnt) * sum_j X[cols[j],:] + bias
__global__ void k_spmm(size_t colsOff, size_t cntOff, size_t XOff,
                       const float* __restrict__ bias, size_t outOff) {
    const int* cols = scri(colsOff);
    const float* X = scr(XOff);
    float* out = scr(outOff);
    __shared__ int sc[MAXNZ];
    int row = blockIdx.x;
    int cnt = scri(cntOff)[row];
    if (threadIdx.x < cnt) sc[threadIdx.x] = cols[(size_t)row * MAXNZ + threadIdx.x];
    __syncthreads();
    float acc = 0.f;
    for (int j = 0; j < cnt; j++) acc += X[(size_t)sc[j] * HH + threadIdx.x];
    float v = cnt > 0 ? (1.0f / (float)cnt) : 0.0f;
    out[(size_t)row * HH + threadIdx.x] = v * acc + bias[threadIdx.x];
}

// ---------------------------------------------------------------------------
// tf32 tensor-core GEMM: C[NN,256] = A[NN,K] @ B[K,256] (+bias)(+relu)
// 128x128 CTA tile, 8 warps (2x4), each warp 64x32 via 4x4 m16n8k8 mma.
// ---------------------------------------------------------------------------
__device__ __forceinline__ uint32_t f2tf(float f) {
    uint32_t r;
    asm("cvt.rna.tf32.f32 %0, %1;" : "=r"(r) : "f"(f));
    return r;
}

__device__ __forceinline__ void mma1688tf(float c[4], const uint32_t a[4], const uint32_t b[2]) {
    asm volatile(
        "mma.sync.aligned.m16n8k8.row.col.f32.tf32.tf32.f32 "
        "{%0,%1,%2,%3}, {%4,%5,%6,%7}, {%8,%9}, {%0,%1,%2,%3};\n"
        : "+f"(c[0]), "+f"(c[1]), "+f"(c[2]), "+f"(c[3])
        : "r"(a[0]), "r"(a[1]), "r"(a[2]), "r"(a[3]), "r"(b[0]), "r"(b[1]));
}

__global__ __launch_bounds__(256) void k_gemm_tc(const float* Aext, size_t AOff,
                                                 const float* __restrict__ B,
                                                 const float* __restrict__ bias,
                                                 size_t COff, int K, int relu) {
    const float* __restrict__ A = Aext ? Aext : scr(AOff);
    float* C = scr(COff);
    __shared__ uint32_t As[128][20];   // row-major, pad 20 -> conflict-free frag reads
    __shared__ uint32_t Bs[16][136];   // k-major,  pad 136 -> conflict-free frag reads
    int tid = threadIdx.x;
    int bn = blockIdx.x * 128, bm = blockIdx.y * 128;
    int wid = tid >> 5, lane = tid & 31;
    int warpM = wid >> 2, warpN = wid & 3;
    int g = lane >> 2, tig = lane & 3;

    float acc[4][4][4];
#pragma unroll
    for (int i = 0; i < 4; i++)
#pragma unroll
        for (int j = 0; j < 4; j++)
#pragma unroll
            for (int q = 0; q < 4; q++) acc[i][j][q] = 0.f;

    for (int k0 = 0; k0 < K; k0 += 16) {
#pragma unroll
        for (int t = 0; t < 2; t++) {
            int idx = tid + 256 * t;
            int r = idx >> 2, kq = (idx & 3) * 4;
            float4 v = *(const float4*)(A + (size_t)(bm + r) * K + k0 + kq);
            uint4 u;
            u.x = f2tf(v.x); u.y = f2tf(v.y); u.z = f2tf(v.z); u.w = f2tf(v.w);
            *(uint4*)&As[r][kq] = u;
            int kb = idx >> 5, nq = (idx & 31) * 4;
            float4 w = *(const float4*)(B + (size_t)(k0 + kb) * HH + bn + nq);
            uint4 x;
            x.x = f2tf(w.x); x.y = f2tf(w.y); x.z = f2tf(w.z); x.w = f2tf(w.w);
            *(uint4*)&Bs[kb][nq] = x;
        }
        __syncthreads();
#pragma unroll
        for (int kk = 0; kk < 16; kk += 8) {
            uint32_t a[4][4], b[4][2];
#pragma unroll
            for (int mt = 0; mt < 4; mt++) {
                int r0 = warpM * 64 + mt * 16;
                a[mt][0] = As[r0 + g][kk + tig];
                a[mt][1] = As[r0 + 8 + g][kk + tig];
                a[mt][2] = As[r0 + g][kk + tig + 4];
                a[mt][3] = As[r0 + 8 + g][kk + tig + 4];
            }
#pragma unroll
            for (int nt = 0; nt < 4; nt++) {
                int c0 = warpN * 32 + nt * 8;
                b[nt][0] = Bs[kk + tig][c0 + g];
                b[nt][1] = Bs[kk + tig + 4][c0 + g];
            }
#pragma unroll
            for (int mt = 0; mt < 4; mt++)
#pragma unroll
                for (int nt = 0; nt < 4; nt++) mma1688tf(acc[mt][nt], a[mt], b[nt]);
        }
        __syncthreads();
    }

    // epilogue: c0 (g, 2tig), c1 (g, 2tig+1), c2 (g+8, 2tig), c3 (g+8, 2tig+1)
#pragma unroll
    for (int mt = 0; mt < 4; mt++) {
        int row0 = bm + warpM * 64 + mt * 16 + g;
#pragma unroll
        for (int nt = 0; nt < 4; nt++) {
            int col = bn + warpN * 32 + nt * 8 + tig * 2;
            float bb0 = bias ? bias[col] : 0.f;
            float bb1 = bias ? bias[col + 1] : 0.f;
            float v0 = acc[mt][nt][0] + bb0, v1 = acc[mt][nt][1] + bb1;
            float v2 = acc[mt][nt][2] + bb0, v3 = acc[mt][nt][3] + bb1;
            if (relu) {
                v0 = fmaxf(v0, 0.f); v1 = fmaxf(v1, 0.f);
                v2 = fmaxf(v2, 0.f); v3 = fmaxf(v3, 0.f);
            }
            float2 p0 = {v0, v1}, p1 = {v2, v3};
            *(float2*)(C + (size_t)row0 * HH + col) = p0;
            *(float2*)(C + (size_t)(row0 + 8) * HH + col) = p1;
        }
    }
}

// Row l2-normalize; optionally emit bf16 copy at bOff (bf16 element offset).
__global__ void k_l2norm(size_t XOff, size_t outOff, int emitB, size_t bOff) {
    const float* X = scr(XOff);
    float* out = scr(outOff);
    int row = blockIdx.x, t = threadIdx.x;
    float x = X[(size_t)row * HH + t];
    float s = x * x;
#pragma unroll
    for (int o = 16; o; o >>= 1) s += __shfl_xor_sync(0xffffffffu, s, o);
    __shared__ float red[8];
    if ((t & 31) == 0) red[t >> 5] = s;
    __syncthreads();
    float tot = 0.f;
#pragma unroll
    for (int i = 0; i < 8; i++) tot += red[i];
    float inv = 1.0f / fmaxf(sqrtf(tot), 1e-12f);
    float y = x * inv;
    out[(size_t)row * HH + t] = y;
    if (emitB) {
        __nv_bfloat16* ob = (__nv_bfloat16*)scr(O_Z1) + bOff;
        ob[(size_t)row * HH + t] = __float2bfloat16(y);
    }
}

__device__ __forceinline__ void mma16816v(float c[4], const uint32_t a[4], const uint32_t b[2]) {
    asm volatile(
        "mma.sync.aligned.m16n8k16.row.col.f32.bf16.bf16.f32 "
        "{%0,%1,%2,%3}, {%4,%5,%6,%7}, {%8,%9}, {%0,%1,%2,%3};\n"
        : "+f"(c[0]), "+f"(c[1]), "+f"(c[2]), "+f"(c[3])
        : "r"(a[0]), "r"(a[1]), "r"(a[2]), "r"(a[3]), "r"(b[0]), "r"(b[1]));
}

// Fused gram: S = A @ B^T (bf16 mma, fp32 accum), exp(S/tau), row/col sums.
__global__ __launch_bounds__(256) void k_gram(size_t AOff, size_t BOff,
                                              size_t rowOff, long long colOff,
                                              int symmetric) {
    int bx = blockIdx.x, by = blockIdx.y;
    if (symmetric && bx < by) return;
    const __nv_bfloat16* A = (const __nv_bfloat16*)scr(O_Z1) + AOff;
    const __nv_bfloat16* Bm = (const __nv_bfloat16*)scr(O_Z1) + BOff;
    float* rowSum = scr(rowOff);
    __shared__ __nv_bfloat16 As[128][40];
    __shared__ __nv_bfloat16 Bs[128][40];
    int tid = threadIdx.x;
    int wid = tid >> 5, lane = tid & 31;
    int warpM = wid >> 2, warpN = wid & 3;
    int g = lane >> 2, tig = lane & 3;
    const int rowBase = by * 128, colBase = bx * 128;

    float acc[4][4][4];
#pragma unroll
    for (int a = 0; a < 4; a++)
#pragma unroll
        for (int b = 0; b < 4; b++)
#pragma unroll
            for (int q = 0; q < 4; q++) acc[a][b][q] = 0.f;

    for (int k0 = 0; k0 < HH; k0 += 32) {
#pragma unroll
        for (int t = 0; t < 2; t++) {
            int idx = tid + t * 256;
            int r = idx >> 2, kq = (idx & 3);
            *(uint4*)(&As[r][kq * 8]) = *(const uint4*)(A + (size_t)(rowBase + r) * HH + k0 + kq * 8);
            *(uint4*)(&Bs[r][kq * 8]) = *(const uint4*)(Bm + (size_t)(colBase + r) * HH + k0 + kq * 8);
        }
        __syncthreads();
#pragma unroll
        for (int kk = 0; kk < 32; kk += 16) {
            uint32_t af[4][4], bf[4][2];
#pragma unroll
            for (int mt = 0; mt < 4; mt++) {
                int r0 = warpM * 64 + mt * 16 + g;
                af[mt][0] = *(const uint32_t*)&As[r0][kk + tig * 2];
                af[mt][1] = *(const uint32_t*)&As[r0 + 8][kk + tig * 2];
                af[mt][2] = *(const uint32_t*)&As[r0][kk + tig * 2 + 8];
                af[mt][3] = *(const uint32_t*)&As[r0 + 8][kk + tig * 2 + 8];
            }
#pragma unroll
            for (int nt = 0; nt < 4; nt++) {
                int c0 = warpN * 32 + nt * 8 + g;
                bf[nt][0] = *(const uint32_t*)&Bs[c0][kk + tig * 2];
                bf[nt][1] = *(const uint32_t*)&Bs[c0][kk + tig * 2 + 8];
            }
#pragma unroll
            for (int mt = 0; mt < 4; mt++)
#pragma unroll
                for (int nt = 0; nt < 4; nt++) mma16816v(acc[mt][nt], af[mt], bf[nt]);
        }
        __syncthreads();
    }

    float rs[4][2], cs[4][2];
#pragma unroll
    for (int i = 0; i < 4; i++) { rs[i][0] = rs[i][1] = 0.f; cs[i][0] = cs[i][1] = 0.f; }
#pragma unroll
    for (int mt = 0; mt < 4; mt++)
#pragma unroll
        for (int nt = 0; nt < 4; nt++) {
            float e0 = exp2f(acc[mt][nt][0] * EXPC);
            float e1 = exp2f(acc[mt][nt][1] * EXPC);
            float e2 = exp2f(acc[mt][nt][2] * EXPC);
            float e3 = exp2f(acc[mt][nt][3] * EXPC);
            rs[mt][0] += e0 + e1; rs[mt][1] += e2 + e3;
            cs[nt][0] += e0 + e2; cs[nt][1] += e1 + e3;
        }
#pragma unroll
    for (int mt = 0; mt < 4; mt++)
#pragma unroll
        for (int h = 0; h < 2; h++) {
            float v = rs[mt][h];
            v += __shfl_xor_sync(0xffffffffu, v, 1);
            v += __shfl_xor_sync(0xffffffffu, v, 2);
            if (tig == 0) {
                int r = rowBase + warpM * 64 + mt * 16 + g + h * 8;
                atomicAdd(&rowSum[r], v);
            }
        }
    bool wantCol = symmetric ? (bx != by) : (colOff >= 0);
    if (wantCol) {
        float* dst = symmetric ? rowSum : scr((size_t)colOff);
#pragma unroll
        for (int nt = 0; nt < 4; nt++)
#pragma unroll
            for (int h = 0; h < 2; h++) {
                float v = cs[nt][h];
                v += __shfl_xor_sync(0xffffffffu, v, 4);
                v += __shfl_xor_sync(0xffffffffu, v, 8);
                v += __shfl_xor_sync(0xffffffffu, v, 16);
                if (g == 0) {
                    int c = colBase + warpN * 32 + nt * 8 + tig * 2 + h;
                    atomicAdd(&dst[c], v);
                }
            }
    }
}

// sii[i] = dot(A_i, B_i) in fp32 (exact diagonal of "between")
__global__ void k_sii(size_t AOff, size_t BOff, size_t sOff) {
    const float* A = scr(AOff);
    const float* B = scr(BOff);
    int w = threadIdx.x >> 5, lane = threadIdx.x & 31;
    int row = blockIdx.x * 8 + w;
    const float* a = A + (size_t)row * HH + lane * 8;
    const float* b = B + (size_t)row * HH + lane * 8;
    float4 a0 = *(const float4*)a, a1 = *(const float4*)(a + 4);
    float4 b0 = *(const float4*)b, b1 = *(const float4*)(b + 4);
    float s = a0.x * b0.x + a0.y * b0.y + a0.z * b0.z + a0.w * b0.w +
              a1.x * b1.x + a1.y * b1.y + a1.z * b1.z + a1.w * b1.w;
#pragma unroll
    for (int o = 16; o; o >>= 1) s += __shfl_xor_sync(0xffffffffu, s, o);
    if (lane == 0) scr(sOff)[row] = s;
}

__global__ void k_semi() {
    int i = blockIdx.x * blockDim.x + threadIdx.x;
    if (i >= NN) return;
    float dl = scr(O_SII)[i] * 2.0f;  // log(diag) = dot/tau
    float l1 = logf(scr(O_R1)[i] + scr(O_BR)[i] - EDIAG) - dl;
    float l2 = logf(scr(O_R2)[i] + scr(O_BC)[i] - EDIAG) - dl;
    scr(O_LSEM)[i] = 0.5f * (l1 + l2);
}

__global__ void k_contrast(const int* __restrict__ nbi, const int* __restrict__ ngi) {
    const float* proj = scr(O_PROJ);
    const float* uemd = scr(O_UEMD);
    const float* vn = scr(O_VN);
    int w = threadIdx.x >> 5, lane = threadIdx.x & 31;
    int n = blockIdx.x * 8 + w;
    float p[8], v[8];
    {
        const float4* pp = (const float4*)(proj + (size_t)n * HH + lane * 8);
        ((float4*)p)[0] = pp[0]; ((float4*)p)[1] = pp[1];
        const float4* vv = (const float4*)(vn + (size_t)n * HH + lane * 8);
        ((float4*)v)[0] = vv[0]; ((float4*)v)[1] = vv[1];
    }
    float posd[SS];
    float negsum = 0.f;
#pragma unroll
    for (int s = 0; s < SS; s++) {
        int nb = nbi[n * SS + s];
        const float4* uu = (const float4*)(uemd + (size_t)nb * HH + lane * 8);
        float u[8]; ((float4*)u)[0] = uu[0]; ((float4*)u)[1] = uu[1];
        float d = 0.f;
#pragma unroll
        for (int k = 0; k < 8; k++) d += p[k] * u[k];
#pragma unroll
        for (int o = 16; o; o >>= 1) d += __shfl_xor_sync(0xffffffffu, d, o);
        posd[s] = d;
        int ng = ngi[n * SS + s];
        const float4* qq = (const float4*)(vn + (size_t)ng * HH + lane * 8);
        float q[8]; ((float4*)q)[0] = qq[0]; ((float4*)q)[1] = qq[1];
        float d2 = 0.f;
#pragma unroll
        for (int k = 0; k < 8; k++) d2 += v[k] * q[k];
#pragma unroll
        for (int o = 16; o; o >>= 1) d2 += __shfl_xor_sync(0xffffffffu, d2, o);
        negsum += exp2f(d2 * EXPC);
    }
    float ns = 0.f, ps = 0.f;
#pragma unroll
    for (int s = 0; s < SS; s++) {
        float pos = exp2f(posd[s] * EXPC);
        ns += logf(pos + negsum);
        ps += posd[s] * 2.0f;  // log(pos) = dot/tau
    }
    if (lane == 0) scr(O_LG)[n] = ns - ps;  // LAMBDA = 1
}

// Deterministic single-block reduction + scalar finalize.
__global__ void k_reduce(float* __restrict__ out) {
    __shared__ float s1[1024], s2[1024];
    int t = threadIdx.x;
    float a = 0.f, b = 0.f;
    for (int i = t; i < NN; i += 1024) { a += scr(O_LG)[i]; b += scr(O_LSEM)[i]; }
    s1[t] = a; s2[t] = b;
    __syncthreads();
    for (int s = 512; s > 0; s >>= 1) {
        if (t < s) { s1[t] += s1[t + s]; s2[t] += s2[t + s]; }
        __syncthreads();
    }
    if (t == 0) {
        float gacl = s1[0] / ((float)NN * (float)SS);
        float sem = s2[0] / (float)NN;
        out[0] = gacl + 0.6f * sem;
        out[1] = gacl;
        out[2] = sem;
    }
}

// Alignment-agnostic copy (dst = out + 3 is NOT 16B aligned).
__global__ void k_copy(size_t srcOff, float* __restrict__ dst, size_t n4) {
    size_t i = (size_t)blockIdx.x * blockDim.x + threadIdx.x;
    if (i < n4) {
        float4 v = ((const float4*)scr(srcOff))[i];
        float* d = dst + i * 4;
        d[0] = v.x; d[1] = v.y; d[2] = v.z; d[3] = v.w;
    }
}

// ---------------------------------------------------------------------------
// Host launch — kernel launches ONLY.
// ---------------------------------------------------------------------------
extern "C" void kernel_launch(void* const* d_in, const int* in_sizes, int n_in,
                              void* d_out, int out_size) {
    const float* adj1 = (const float*)d_in[0];
    const float* adj2 = (const float*)d_in[1];
    const float* x1 = (const float*)d_in[2];
    const float* x2 = (const float*)d_in[3];
    const int* nbi = (const int*)d_in[4];
    const int* ngi = (const int*)d_in[5];
    const float* W1 = (const float*)d_in[6];
    const float* b1 = (const float*)d_in[7];
    const float* W2 = (const float*)d_in[8];
    const float* b2 = (const float*)d_in[9];
    const float* tW1 = (const float*)d_in[10];
    const float* tb1 = (const float*)d_in[11];
    const float* tW2 = (const float*)d_in[12];
    const float* tb2 = (const float*)d_in[13];
    const float* pW0 = (const float*)d_in[14];
    const float* pB0 = (const float*)d_in[15];
    const float* pW1 = (const float*)d_in[16];
    const float* pB1 = (const float*)d_in[17];
    const float* pW2 = (const float*)d_in[18];
    const float* pB2 = (const float*)d_in[19];
    const float* sW0 = (const float*)d_in[20];
    const float* sB0 = (const float*)d_in[21];
    const float* sW1 = (const float*)d_in[22];
    const float* sB1 = (const float*)d_in[23];
    const float* sW2 = (const float*)d_in[24];
    const float* sB2 = (const float*)d_in[25];

    float* out = (float*)d_out;
    size_t h3_off = (size_t)out_size - NH;  // scalars precede h3

    dim3 gemmGrid(2, NN / 128);
    dim3 gramGrid(128, 128);

    k_zero4<<<NN / 256, 256>>>();
    k_extract<<<NN, 256>>>(adj1, O_COLS1, O_CNT1);
    k_extract<<<NN, 256>>>(adj2, O_COLS2, O_CNT2);

    // stage A: X @ W (bias deferred to spmm)
    k_gemm_tc<<<gemmGrid, 256>>>(x1, 0, W1, nullptr, O_P1, DIN, 0);
    k_gemm_tc<<<gemmGrid, 256>>>(x2, 0, W1, nullptr, O_P2, DIN, 0);
    k_gemm_tc<<<gemmGrid, 256>>>(x1, 0, tW1, nullptr, O_T1, DIN, 0);

    // graph convs (sparse)
    k_spmm<<<NN, 256>>>(O_COLS1, O_CNT1, O_P1, b1, O_H1);
    k_spmm<<<NN, 256>>>(O_COLS1, O_CNT1, O_P2, b1, O_H2);
    k_spmm<<<NN, 256>>>(O_COLS2, O_CNT2, O_P1, b1, O_G3A);
    k_spmm<<<NN, 256>>>(O_COLS2, O_CNT2, O_T1, tb1, O_UA);

    k_gemm_tc<<<gemmGrid, 256>>>(nullptr, O_G3A, W2, nullptr, O_G3B, HH, 0);
    k_gemm_tc<<<gemmGrid, 256>>>(nullptr, O_UA, tW2, nullptr, O_UB, HH, 0);

    k_spmm<<<NN, 256>>>(O_COLS2, O_CNT2, O_G3B, b2, O_H3);
    k_spmm<<<NN, 256>>>(O_COLS2, O_CNT2, O_UB, tb2, O_U);

    k_l2norm<<<NN, 256>>>(O_U, O_UEMD, 0, 0);
    k_l2norm<<<NN, 256>>>(O_H3, O_VN, 0, 0);

    // projection MLP on h3
    k_gemm_tc<<<gemmGrid, 256>>>(nullptr, O_H3, pW0, pB0, O_T0, HH, 1);
    k_gemm_tc<<<gemmGrid, 256>>>(nullptr, O_T0, pW1, pB1, O_TT1, HH, 1);
    k_gemm_tc<<<gemmGrid, 256>>>(nullptr, O_TT1, pW2, pB2, O_T0, HH, 0);
    k_l2norm<<<NN, 256>>>(O_T0, O_PROJ, 0, 0);

    // semantic MLP on h1 -> h1p (+bf16 Z1)
    k_gemm_tc<<<gemmGrid, 256>>>(nullptr, O_H1, sW0, sB0, O_T0, HH, 1);
    k_gemm_tc<<<gemmGrid, 256>>>(nullptr, O_T0, sW1, sB1, O_TT1, HH, 1);
    k_gemm_tc<<<gemmGrid, 256>>>(nullptr, O_TT1, sW2, sB2, O_T0, HH, 0);
    k_l2norm<<<NN, 256>>>(O_T0, O_H1P, 1, 0);

    // semantic MLP on h2 -> h2p (+bf16 Z2)
    k_gemm_tc<<<gemmGrid, 256>>>(nullptr, O_H2, sW0, sB0, O_T0, HH, 1);
    k_gemm_tc<<<gemmGrid, 256>>>(nullptr, O_T0, sW1, sB1, O_TT1, HH, 1);
    k_gemm_tc<<<gemmGrid, 256>>>(nullptr, O_TT1, sW2, sB2, O_T0, HH, 0);
    k_l2norm<<<NN, 256>>>(O_T0, O_H2P, 1, NH);

    // fused exp-gram row/col sums
    k_gram<<<gramGrid, 256>>>(0, 0, O_R1, -1, 1);
    k_gram<<<gramGrid, 256>>>(NH, NH, O_R2, -1, 1);
    k_gram<<<gramGrid, 256>>>(0, NH, O_BR, (long long)O_BC, 0);

    k_sii<<<NN / 8, 256>>>(O_H1P, O_H2P, O_SII);
    k_semi<<<NN / 256, 256>>>();
    k_contrast<<<NN / 8, 256>>>(nbi, ngi);

    k_reduce<<<1, 1024>>>(out);
    k_copy<<<(unsigned)((NH / 4 + 255) / 256), 256>>>(O_H3, out + h3_off, NH / 4);
}

// round 5
// speedup vs baseline: 1.4211x; 1.0830x over previous
#include <cuda_runtime.h>
#include <cuda_bf16.h>
#include <cstdint>
#include <cstddef>

#define NN 16384
#define HH 256
#define DIN 512
#define SS 8
#define MAXNZ 64
#define NH 4194304UL  // NN*HH floats

#define EXPC 2.8853900817779268f   // log2(e)/tau, tau=0.5
#define EDIAG 7.389056098930650f   // exp(2)

// ---------------------------------------------------------------------------
// Scratch
// ---------------------------------------------------------------------------
__device__ float g_scratch[21 * NH + 2 * (NN * MAXNZ) + 2 * NN + 8 * NN];

#define O_P1    (0 * NH)
#define O_P2    (1 * NH)
#define O_T1    (2 * NH)
#define O_H1    (3 * NH)   // H1,H2 contiguous (batched semantic MLP input)
#define O_H2    (4 * NH)
#define O_G3A   (5 * NH)
#define O_G3B   (6 * NH)
#define O_H3    (7 * NH)
#define O_UA    (8 * NH)
#define O_UB    (9 * NH)
#define O_U     (10 * NH)
#define O_PAIRA (11 * NH)  // 2*NH pair buffer
#define O_PAIRB (13 * NH)  // 2*NH pair buffer
#define O_PROJ  (15 * NH)
#define O_H1P   (16 * NH)  // H1P,H2P contiguous
#define O_H2P   (17 * NH)
#define O_VN    (18 * NH)
#define O_UEMD  (19 * NH)
#define O_Z1    (20 * NH)  // bf16: Z1 (NH) then Z2 (NH)
#define O_TAIL  (21 * NH)
#define O_COLS1 (O_TAIL)
#define O_COLS2 (O_COLS1 + (size_t)NN * MAXNZ)
#define O_CNT1  (O_COLS2 + (size_t)NN * MAXNZ)
#define O_CNT2  (O_CNT1 + NN)
#define O_R1    (O_CNT2 + NN)
#define O_R2    (O_R1 + NN)
#define O_BR    (O_R2 + NN)
#define O_BC    (O_BR + NN)
#define O_SII   (O_BC + NN)
#define O_LSEM  (O_SII + NN)
#define O_LG    (O_LSEM + NN)

__device__ __forceinline__ float* scr(size_t off) { return g_scratch + off; }
__device__ __forceinline__ int* scri(size_t off) { return (int*)(g_scratch + off); }

// ---------------------------------------------------------------------------
// PTX helpers
// ---------------------------------------------------------------------------
__device__ __forceinline__ uint32_t f2tf(float f) {
    uint32_t r;
    asm("cvt.rna.tf32.f32 %0, %1;" : "=r"(r) : "f"(f));
    return r;
}
__device__ __forceinline__ void mma1688tf(float c[4], const uint32_t a[4], const uint32_t b[2]) {
    asm volatile(
        "mma.sync.aligned.m16n8k8.row.col.f32.tf32.tf32.f32 "
        "{%0,%1,%2,%3}, {%4,%5,%6,%7}, {%8,%9}, {%0,%1,%2,%3};\n"
        : "+f"(c[0]), "+f"(c[1]), "+f"(c[2]), "+f"(c[3])
        : "r"(a[0]), "r"(a[1]), "r"(a[2]), "r"(a[3]), "r"(b[0]), "r"(b[1]));
}
__device__ __forceinline__ void mma16816v(float c[4], const uint32_t a[4], const uint32_t b[2]) {
    asm volatile(
        "mma.sync.aligned.m16n8k16.row.col.f32.bf16.bf16.f32 "
        "{%0,%1,%2,%3}, {%4,%5,%6,%7}, {%8,%9}, {%0,%1,%2,%3};\n"
        : "+f"(c[0]), "+f"(c[1]), "+f"(c[2]), "+f"(c[3])
        : "r"(a[0]), "r"(a[1]), "r"(a[2]), "r"(a[3]), "r"(b[0]), "r"(b[1]));
}
__device__ __forceinline__ uint32_t s2u(const void* p) {
    return (uint32_t)__cvta_generic_to_shared(p);
}
__device__ __forceinline__ void cpasync16(uint32_t dst, const void* src) {
    asm volatile("cp.async.cg.shared.global [%0], [%1], 16;" :: "r"(dst), "l"(src));
}
#define CP_COMMIT() asm volatile("cp.async.commit_group;")
#define CP_WAIT1()  asm volatile("cp.async.wait_group 1;")
__device__ __forceinline__ void ldsm_x4(uint32_t r[4], uint32_t addr) {
    asm volatile("ldmatrix.sync.aligned.m8n8.x4.shared.b16 {%0,%1,%2,%3}, [%4];"
                 : "=r"(r[0]), "=r"(r[1]), "=r"(r[2]), "=r"(r[3]) : "r"(addr));
}
__device__ __forceinline__ void ldsm_x2(uint32_t r[2], uint32_t addr) {
    asm volatile("ldmatrix.sync.aligned.m8n8.x2.shared.b16 {%0,%1}, [%2];"
                 : "=r"(r[0]), "=r"(r[1]) : "r"(addr));
}

// ---------------------------------------------------------------------------

__global__ void k_zero4() {
    int i = blockIdx.x * blockDim.x + threadIdx.x;
    if (i < NN) {
        scr(O_R1)[i] = 0.f; scr(O_R2)[i] = 0.f;
        scr(O_BR)[i] = 0.f; scr(O_BC)[i] = 0.f;
    }
}

__global__ void k_extract(const float* __restrict__ adj, size_t colsOff, size_t cntOff) {
    int* cols = scri(colsOff);
    int* cnts = scri(cntOff);
    int row = blockIdx.x;
    __shared__ int scnt;
    if (threadIdx.x == 0) scnt = 0;
    __syncthreads();
    const float4* a4 = (const float4*)(adj + (size_t)row * NN);
    for (int i = threadIdx.x; i < NN / 4; i += blockDim.x) {
        float4 v = a4[i];
        int base = i * 4;
        if (v.x != 0.f) { int s = atomicAdd(&scnt, 1); if (s < MAXNZ) cols[(size_t)row * MAXNZ + s] = base + 0; }
        if (v.y != 0.f) { int s = atomicAdd(&scnt, 1); if (s < MAXNZ) cols[(size_t)row * MAXNZ + s] = base + 1; }
        if (v.z != 0.f) { int s = atomicAdd(&scnt, 1); if (s < MAXNZ) cols[(size_t)row * MAXNZ + s] = base + 2; }
        if (v.w != 0.f) { int s = atomicAdd(&scnt, 1); if (s < MAXNZ) cols[(size_t)row * MAXNZ + s] = base + 3; }
    }
    __syncthreads();
    if (threadIdx.x == 0) cnts[row] = scnt > MAXNZ ? MAXNZ : scnt;
}

__global__ void k_spmm(size_t colsOff, size_t cntOff, size_t XOff,
                       const float* __restrict__ bias, size_t outOff) {
    const int* cols = scri(colsOff);
    const float* X = scr(XOff);
    float* out = scr(outOff);
    __shared__ int sc[MAXNZ];
    int row = blockIdx.x;
    int cnt = scri(cntOff)[row];
    if (threadIdx.x < cnt) sc[threadIdx.x] = cols[(size_t)row * MAXNZ + threadIdx.x];
    __syncthreads();
    float acc = 0.f;
    for (int j = 0; j < cnt; j++) acc += X[(size_t)sc[j] * HH + threadIdx.x];
    float v = cnt > 0 ? (1.0f / (float)cnt) : 0.0f;
    out[(size_t)row * HH + threadIdx.x] = v * acc + bias[threadIdx.x];
}

// ---------------------------------------------------------------------------
// tf32 GEMM, register-staged double-buffered smem. C[M,256] = A[M,K]@B[K,256]
// ---------------------------------------------------------------------------
__global__ __launch_bounds__(256) void k_gemm_tc(const float* Aext, size_t AOff,
                                                 const float* __restrict__ B,
                                                 const float* __restrict__ bias,
                                                 size_t COff, int K, int relu) {
    const float* __restrict__ A = Aext ? Aext : scr(AOff);
    float* C = scr(COff);
    __shared__ uint32_t As[2][128][20];
    __shared__ uint32_t Bs[2][16][136];
    int tid = threadIdx.x;
    int bn = blockIdx.x * 128, bm = blockIdx.y * 128;
    int wid = tid >> 5, lane = tid & 31;
    int warpM = wid >> 2, warpN = wid & 3;
    int g = lane >> 2, tig = lane & 3;

    // staged-load thread coordinates (fixed)
    int rA0 = tid >> 2, kqA0 = (tid & 3) * 4;
    int rA1 = (tid + 256) >> 2, kqA1 = ((tid + 256) & 3) * 4;
    int kB0 = tid >> 5, nB0 = (tid & 31) * 4;
    int kB1 = (tid + 256) >> 5, nB1 = ((tid + 256) & 31) * 4;

    float4 ra0, ra1, rb0, rb1;
    auto loadT = [&](int t) {
        int k0 = t * 16;
        ra0 = *(const float4*)(A + (size_t)(bm + rA0) * K + k0 + kqA0);
        ra1 = *(const float4*)(A + (size_t)(bm + rA1) * K + k0 + kqA1);
        rb0 = *(const float4*)(B + (size_t)(k0 + kB0) * HH + bn + nB0);
        rb1 = *(const float4*)(B + (size_t)(k0 + kB1) * HH + bn + nB1);
    };
    auto storeT = [&](int buf) {
        uint4 u0 = {f2tf(ra0.x), f2tf(ra0.y), f2tf(ra0.z), f2tf(ra0.w)};
        uint4 u1 = {f2tf(ra1.x), f2tf(ra1.y), f2tf(ra1.z), f2tf(ra1.w)};
        uint4 v0 = {f2tf(rb0.x), f2tf(rb0.y), f2tf(rb0.z), f2tf(rb0.w)};
        uint4 v1 = {f2tf(rb1.x), f2tf(rb1.y), f2tf(rb1.z), f2tf(rb1.w)};
        *(uint4*)&As[buf][rA0][kqA0] = u0;
        *(uint4*)&As[buf][rA1][kqA1] = u1;
        *(uint4*)&Bs[buf][kB0][nB0] = v0;
        *(uint4*)&Bs[buf][kB1][nB1] = v1;
    };

    float acc[4][4][4];
#pragma unroll
    for (int i = 0; i < 4; i++)
#pragma unroll
        for (int j = 0; j < 4; j++)
#pragma unroll
            for (int q = 0; q < 4; q++) acc[i][j][q] = 0.f;

    int T = K / 16;
    loadT(0);
    storeT(0);
    __syncthreads();
    for (int t = 0; t < T; t++) {
        int buf = t & 1;
        if (t + 1 < T) loadT(t + 1);
#pragma unroll
        for (int kk = 0; kk < 16; kk += 8) {
            uint32_t a[4][4], b[4][2];
#pragma unroll
            for (int mt = 0; mt < 4; mt++) {
                int r0 = warpM * 64 + mt * 16;
                a[mt][0] = As[buf][r0 + g][kk + tig];
                a[mt][1] = As[buf][r0 + 8 + g][kk + tig];
                a[mt][2] = As[buf][r0 + g][kk + tig + 4];
                a[mt][3] = As[buf][r0 + 8 + g][kk + tig + 4];
            }
#pragma unroll
            for (int nt = 0; nt < 4; nt++) {
                int c0 = warpN * 32 + nt * 8;
                b[nt][0] = Bs[buf][kk + tig][c0 + g];
                b[nt][1] = Bs[buf][kk + tig + 4][c0 + g];
            }
#pragma unroll
            for (int mt = 0; mt < 4; mt++)
#pragma unroll
                for (int nt = 0; nt < 4; nt++) mma1688tf(acc[mt][nt], a[mt], b[nt]);
        }
        if (t + 1 < T) storeT((t + 1) & 1);
        __syncthreads();
    }

#pragma unroll
    for (int mt = 0; mt < 4; mt++) {
        int row0 = bm + warpM * 64 + mt * 16 + g;
#pragma unroll
        for (int nt = 0; nt < 4; nt++) {
            int col = bn + warpN * 32 + nt * 8 + tig * 2;
            float bb0 = bias ? bias[col] : 0.f;
            float bb1 = bias ? bias[col + 1] : 0.f;
            float v0 = acc[mt][nt][0] + bb0, v1 = acc[mt][nt][1] + bb1;
            float v2 = acc[mt][nt][2] + bb0, v3 = acc[mt][nt][3] + bb1;
            if (relu) {
                v0 = fmaxf(v0, 0.f); v1 = fmaxf(v1, 0.f);
                v2 = fmaxf(v2, 0.f); v3 = fmaxf(v3, 0.f);
            }
            float2 p0 = {v0, v1}, p1 = {v2, v3};
            *(float2*)(C + (size_t)row0 * HH + col) = p0;
            *(float2*)(C + (size_t)(row0 + 8) * HH + col) = p1;
        }
    }
}

// Row l2-normalize; optionally emit bf16 copy at bOff (bf16 element offset).
__global__ void k_l2norm(size_t XOff, size_t outOff, int emitB, size_t bOff) {
    const float* X = scr(XOff);
    float* out = scr(outOff);
    int row = blockIdx.x, t = threadIdx.x;
    float x = X[(size_t)row * HH + t];
    float s = x * x;
#pragma unroll
    for (int o = 16; o; o >>= 1) s += __shfl_xor_sync(0xffffffffu, s, o);
    __shared__ float red[8];
    if ((t & 31) == 0) red[t >> 5] = s;
    __syncthreads();
    float tot = 0.f;
#pragma unroll
    for (int i = 0; i < 8; i++) tot += red[i];
    float inv = 1.0f / fmaxf(sqrtf(tot), 1e-12f);
    float y = x * inv;
    out[(size_t)row * HH + t] = y;
    if (emitB) {
        __nv_bfloat16* ob = (__nv_bfloat16*)scr(O_Z1) + bOff;
        ob[(size_t)row * HH + t] = __float2bfloat16(y);
    }
}

// ---------------------------------------------------------------------------
// Fused exp-gram, cp.async double buffer + ldmatrix fragments.
// ---------------------------------------------------------------------------
__global__ __launch_bounds__(256) void k_gram(size_t AOff, size_t BOff,
                                              size_t rowOff, long long colOff,
                                              int symmetric) {
    int bx = blockIdx.x, by = blockIdx.y;
    if (symmetric && bx < by) return;
    const __nv_bfloat16* A = (const __nv_bfloat16*)scr(O_Z1) + AOff;
    const __nv_bfloat16* Bm = (const __nv_bfloat16*)scr(O_Z1) + BOff;
    float* rowSum = scr(rowOff);
    __shared__ __nv_bfloat16 As[2][128][40];
    __shared__ __nv_bfloat16 Bs[2][128][40];
    int tid = threadIdx.x;
    int wid = tid >> 5, lane = tid & 31;
    int warpM = wid >> 2, warpN = wid & 3;
    int g = lane >> 2, tig = lane & 3;
    const int rowBase = by * 128, colBase = bx * 128;

    int rL0 = tid >> 2, kL0 = (tid & 3) * 8;
    int rL1 = (tid + 256) >> 2, kL1 = ((tid + 256) & 3) * 8;

    auto prefetch = [&](int t, int buf) {
        int k0 = t * 32;
        cpasync16(s2u(&As[buf][rL0][kL0]), A + (size_t)(rowBase + rL0) * HH + k0 + kL0);
        cpasync16(s2u(&As[buf][rL1][kL1]), A + (size_t)(rowBase + rL1) * HH + k0 + kL1);
        cpasync16(s2u(&Bs[buf][rL0][kL0]), Bm + (size_t)(colBase + rL0) * HH + k0 + kL0);
        cpasync16(s2u(&Bs[buf][rL1][kL1]), Bm + (size_t)(colBase + rL1) * HH + k0 + kL1);
    };

    float acc[4][4][4];
#pragma unroll
    for (int a = 0; a < 4; a++)
#pragma unroll
        for (int b = 0; b < 4; b++)
#pragma unroll
            for (int q = 0; q < 4; q++) acc[a][b][q] = 0.f;

    const int T = HH / 32;  // 8
    prefetch(0, 0);
    CP_COMMIT();
    for (int t = 0; t < T; t++) {
        int buf = t & 1;
        if (t + 1 < T) prefetch(t + 1, (t + 1) & 1);
        CP_COMMIT();
        CP_WAIT1();
        __syncthreads();
        uint32_t asb = s2u(&As[buf][0][0]);
        uint32_t bsb = s2u(&Bs[buf][0][0]);
#pragma unroll
        for (int kk = 0; kk < 32; kk += 16) {
            uint32_t af[4][4], bf[4][2];
#pragma unroll
            for (int mt = 0; mt < 4; mt++) {
                int row = warpM * 64 + mt * 16 + (lane & 15);
                int col = kk + ((lane >> 4) << 3);
                ldsm_x4(af[mt], asb + (row * 40 + col) * 2);
            }
#pragma unroll
            for (int nt = 0; nt < 4; nt++) {
                int row = warpN * 32 + nt * 8 + (lane & 7);
                int col = kk + (((lane >> 3) & 1) << 3);
                ldsm_x2(bf[nt], bsb + (row * 40 + col) * 2);
            }
#pragma unroll
            for (int mt = 0; mt < 4; mt++)
#pragma unroll
                for (int nt = 0; nt < 4; nt++) mma16816v(acc[mt][nt], af[mt], bf[nt]);
        }
        __syncthreads();
    }

    float rs[4][2], cs[4][2];
#pragma unroll
    for (int i = 0; i < 4; i++) { rs[i][0] = rs[i][1] = 0.f; cs[i][0] = cs[i][1] = 0.f; }
#pragma unroll
    for (int mt = 0; mt < 4; mt++)
#pragma unroll
        for (int nt = 0; nt < 4; nt++) {
            float e0 = exp2f(acc[mt][nt][0] * EXPC);
            float e1 = exp2f(acc[mt][nt][1] * EXPC);
            float e2 = exp2f(acc[mt][nt][2] * EXPC);
            float e3 = exp2f(acc[mt][nt][3] * EXPC);
            rs[mt][0] += e0 + e1; rs[mt][1] += e2 + e3;
            cs[nt][0] += e0 + e2; cs[nt][1] += e1 + e3;
        }
#pragma unroll
    for (int mt = 0; mt < 4; mt++)
#pragma unroll
        for (int h = 0; h < 2; h++) {
            float v = rs[mt][h];
            v += __shfl_xor_sync(0xffffffffu, v, 1);
            v += __shfl_xor_sync(0xffffffffu, v, 2);
            if (tig == 0) {
                int r = rowBase + warpM * 64 + mt * 16 + g + h * 8;
                atomicAdd(&rowSum[r], v);
            }
        }
    bool wantCol = symmetric ? (bx != by) : (colOff >= 0);
    if (wantCol) {
        float* dst = symmetric ? rowSum : scr((size_t)colOff);
#pragma unroll
        for (int nt = 0; nt < 4; nt++)
#pragma unroll
            for (int h = 0; h < 2; h++) {
                float v = cs[nt][h];
                v += __shfl_xor_sync(0xffffffffu, v, 4);
                v += __shfl_xor_sync(0xffffffffu, v, 8);
                v += __shfl_xor_sync(0xffffffffu, v, 16);
                if (g == 0) {
                    int c = colBase + warpN * 32 + nt * 8 + tig * 2 + h;
                    atomicAdd(&dst[c], v);
                }
            }
    }
}

// sii[i] = dot(A_i, B_i) fp32
__global__ void k_sii(size_t AOff, size_t BOff, size_t sOff) {
    const float* A = scr(AOff);
    const float* B = scr(BOff);
    int w = threadIdx.x >> 5, lane = threadIdx.x & 31;
    int row = blockIdx.x * 8 + w;
    const float* a = A + (size_t)row * HH + lane * 8;
    const float* b = B + (size_t)row * HH + lane * 8;
    float4 a0 = *(const float4*)a, a1 = *(const float4*)(a + 4);
    float4 b0 = *(const float4*)b, b1 = *(const float4*)(b + 4);
    float s = a0.x * b0.x + a0.y * b0.y + a0.z * b0.z + a0.w * b0.w +
              a1.x * b1.x + a1.y * b1.y + a1.z * b1.z + a1.w * b1.w;
#pragma unroll
    for (int o = 16; o; o >>= 1) s += __shfl_xor_sync(0xffffffffu, s, o);
    if (lane == 0) scr(sOff)[row] = s;
}

__global__ void k_semi() {
    int i = blockIdx.x * blockDim.x + threadIdx.x;
    if (i >= NN) return;
    float dl = scr(O_SII)[i] * 2.0f;
    float l1 = logf(scr(O_R1)[i] + scr(O_BR)[i] - EDIAG) - dl;
    float l2 = logf(scr(O_R2)[i] + scr(O_BC)[i] - EDIAG) - dl;
    scr(O_LSEM)[i] = 0.5f * (l1 + l2);
}

__global__ void k_contrast(const int* __restrict__ nbi, const int* __restrict__ ngi) {
    const float* proj = scr(O_PROJ);
    const float* uemd = scr(O_UEMD);
    const float* vn = scr(O_VN);
    int w = threadIdx.x >> 5, lane = threadIdx.x & 31;
    int n = blockIdx.x * 8 + w;
    float p[8], v[8];
    {
        const float4* pp = (const float4*)(proj + (size_t)n * HH + lane * 8);
        ((float4*)p)[0] = pp[0]; ((float4*)p)[1] = pp[1];
        const float4* vv = (const float4*)(vn + (size_t)n * HH + lane * 8);
        ((float4*)v)[0] = vv[0]; ((float4*)v)[1] = vv[1];
    }
    float posd[SS];
    float negsum = 0.f;
#pragma unroll
    for (int s = 0; s < SS; s++) {
        int nb = nbi[n * SS + s];
        const float4* uu = (const float4*)(uemd + (size_t)nb * HH + lane * 8);
        float u[8]; ((float4*)u)[0] = uu[0]; ((float4*)u)[1] = uu[1];
        float d = 0.f;
#pragma unroll
        for (int k = 0; k < 8; k++) d += p[k] * u[k];
#pragma unroll
        for (int o = 16; o; o >>= 1) d += __shfl_xor_sync(0xffffffffu, d, o);
        posd[s] = d;
        int ng = ngi[n * SS + s];
        const float4* qq = (const float4*)(vn + (size_t)ng * HH + lane * 8);
        float q[8]; ((float4*)q)[0] = qq[0]; ((float4*)q)[1] = qq[1];
        float d2 = 0.f;
#pragma unroll
        for (int k = 0; k < 8; k++) d2 += v[k] * q[k];
#pragma unroll
        for (int o = 16; o; o >>= 1) d2 += __shfl_xor_sync(0xffffffffu, d2, o);
        negsum += exp2f(d2 * EXPC);
    }
    float ns = 0.f, ps = 0.f;
#pragma unroll
    for (int s = 0; s < SS; s++) {
        float pos = exp2f(posd[s] * EXPC);
        ns += logf(pos + negsum);
        ps += posd[s] * 2.0f;
    }
    if (lane == 0) scr(O_LG)[n] = ns - ps;
}

__global__ void k_reduce(float* __restrict__ out) {
    __shared__ float s1[1024], s2[1024];
    int t = threadIdx.x;
    float a = 0.f, b = 0.f;
    for (int i = t; i < NN; i += 1024) { a += scr(O_LG)[i]; b += scr(O_LSEM)[i]; }
    s1[t] = a; s2[t] = b;
    __syncthreads();
    for (int s = 512; s > 0; s >>= 1) {
        if (t < s) { s1[t] += s1[t + s]; s2[t] += s2[t + s]; }
        __syncthreads();
    }
    if (t == 0) {
        float gacl = s1[0] / ((float)NN * (float)SS);
        float sem = s2[0] / (float)NN;
        out[0] = gacl + 0.6f * sem;
        out[1] = gacl;
        out[2] = sem;
    }
}

// Alignment-agnostic copy (dst = out + 3 is NOT 16B aligned).
__global__ void k_copy(size_t srcOff, float* __restrict__ dst, size_t n4) {
    size_t i = (size_t)blockIdx.x * blockDim.x + threadIdx.x;
    if (i < n4) {
        float4 v = ((const float4*)scr(srcOff))[i];
        float* d = dst + i * 4;
        d[0] = v.x; d[1] = v.y; d[2] = v.z; d[3] = v.w;
    }
}

// ---------------------------------------------------------------------------
extern "C" void kernel_launch(void* const* d_in, const int* in_sizes, int n_in,
                              void* d_out, int out_size) {
    const float* adj1 = (const float*)d_in[0];
    const float* adj2 = (const float*)d_in[1];
    const float* x1 = (const float*)d_in[2];
    const float* x2 = (const float*)d_in[3];
    const int* nbi = (const int*)d_in[4];
    const int* ngi = (const int*)d_in[5];
    const float* W1 = (const float*)d_in[6];
    const float* b1 = (const float*)d_in[7];
    const float* W2 = (const float*)d_in[8];
    const float* b2 = (const float*)d_in[9];
    const float* tW1 = (const float*)d_in[10];
    const float* tb1 = (const float*)d_in[11];
    const float* tW2 = (const float*)d_in[12];
    const float* tb2 = (const float*)d_in[13];
    const float* pW0 = (const float*)d_in[14];
    const float* pB0 = (const float*)d_in[15];
    const float* pW1 = (const float*)d_in[16];
    const float* pB1 = (const float*)d_in[17];
    const float* pW2 = (const float*)d_in[18];
    const float* pB2 = (const float*)d_in[19];
    const float* sW0 = (const float*)d_in[20];
    const float* sB0 = (const float*)d_in[21];
    const float* sW1 = (const float*)d_in[22];
    const float* sB1 = (const float*)d_in[23];
    const float* sW2 = (const float*)d_in[24];
    const float* sB2 = (const float*)d_in[25];

    float* out = (float*)d_out;
    size_t h3_off = (size_t)out_size - NH;

    dim3 gemmGrid(2, NN / 128);
    dim3 gemmGrid2(2, 2 * NN / 128);  // batched M = 2*NN
    dim3 gramGrid(128, 128);

    k_zero4<<<NN / 256, 256>>>();
    k_extract<<<NN, 256>>>(adj1, O_COLS1, O_CNT1);
    k_extract<<<NN, 256>>>(adj2, O_COLS2, O_CNT2);

    // stage A: X @ W (bias deferred to spmm)
    k_gemm_tc<<<gemmGrid, 256>>>(x1, 0, W1, nullptr, O_P1, DIN, 0);
    k_gemm_tc<<<gemmGrid, 256>>>(x2, 0, W1, nullptr, O_P2, DIN, 0);
    k_gemm_tc<<<gemmGrid, 256>>>(x1, 0, tW1, nullptr, O_T1, DIN, 0);

    // graph convs (sparse)
    k_spmm<<<NN, 256>>>(O_COLS1, O_CNT1, O_P1, b1, O_H1);
    k_spmm<<<NN, 256>>>(O_COLS1, O_CNT1, O_P2, b1, O_H2);
    k_spmm<<<NN, 256>>>(O_COLS2, O_CNT2, O_P1, b1, O_G3A);
    k_spmm<<<NN, 256>>>(O_COLS2, O_CNT2, O_T1, tb1, O_UA);

    k_gemm_tc<<<gemmGrid, 256>>>(nullptr, O_G3A, W2, nullptr, O_G3B, HH, 0);
    k_gemm_tc<<<gemmGrid, 256>>>(nullptr, O_UA, tW2, nullptr, O_UB, HH, 0);

    k_spmm<<<NN, 256>>>(O_COLS2, O_CNT2, O_G3B, b2, O_H3);
    k_spmm<<<NN, 256>>>(O_COLS2, O_CNT2, O_UB, tb2, O_U);

    k_l2norm<<<NN, 256>>>(O_U, O_UEMD, 0, 0);
    k_l2norm<<<NN, 256>>>(O_H3, O_VN, 0, 0);

    // projection MLP on h3
    k_gemm_tc<<<gemmGrid, 256>>>(nullptr, O_H3, pW0, pB0, O_PAIRA, HH, 1);
    k_gemm_tc<<<gemmGrid, 256>>>(nullptr, O_PAIRA, pW1, pB1, O_PAIRB, HH, 1);
    k_gemm_tc<<<gemmGrid, 256>>>(nullptr, O_PAIRB, pW2, pB2, O_PAIRA, HH, 0);
    k_l2norm<<<NN, 256>>>(O_PAIRA, O_PROJ, 0, 0);

    // batched semantic MLP on [h1; h2] (M = 2*NN)
    k_gemm_tc<<<gemmGrid2, 256>>>(nullptr, O_H1, sW0, sB0, O_PAIRA, HH, 1);
    k_gemm_tc<<<gemmGrid2, 256>>>(nullptr, O_PAIRA, sW1, sB1, O_PAIRB, HH, 1);
    k_gemm_tc<<<gemmGrid2, 256>>>(nullptr, O_PAIRB, sW2, sB2, O_PAIRA, HH, 0);
    k_l2norm<<<2 * NN, 256>>>(O_PAIRA, O_H1P, 1, 0);  // h1p,h2p + Z1,Z2

    // fused exp-gram row/col sums
    k_gram<<<gramGrid, 256>>>(0, 0, O_R1, -1, 1);
    k_gram<<<gramGrid, 256>>>(NH, NH, O_R2, -1, 1);
    k_gram<<<gramGrid, 256>>>(0, NH, O_BR, (long long)O_BC, 0);

    k_sii<<<NN / 8, 256>>>(O_H1P, O_H2P, O_SII);
    k_semi<<<NN / 256, 256>>>();
    k_contrast<<<NN / 8, 256>>>(nbi, ngi);

    k_reduce<<<1, 1024>>>(out);
    k_copy<<<(unsigned)((NH / 4 + 255) / 256), 256>>>(O_H3, out + h3_off, NH / 4);
}

// round 6
// speedup vs baseline: 1.4796x; 1.0412x over previous
#include <cuda_runtime.h>
#include <cuda_bf16.h>
#include <cstdint>
#include <cstddef>

#define NN 16384
#define HH 256
#define DIN 512
#define SS 8
#define MAXNZ 64
#define NH 4194304UL  // NN*HH floats

#define EXPC 2.8853900817779268f   // log2(e)/tau, tau=0.5
#define EDIAG 7.389056098930650f   // exp(2)

// ---------------------------------------------------------------------------
// Scratch
// ---------------------------------------------------------------------------
__device__ float g_scratch[23 * NH + 2 * (NN * MAXNZ) + 2 * NN + 8 * NN];

#define O_P1    (0 * NH)   // P1,P2 contiguous (dual stage-A output)
#define O_P2    (1 * NH)
#define O_T1    (2 * NH)
#define O_H3    (3 * NH)   // H3,H1,H2 contiguous (batched MLP input)
#define O_H1    (4 * NH)
#define O_H2    (5 * NH)
#define O_G3A   (6 * NH)   // G3A,UA contiguous (selector GEMM input)
#define O_UA    (7 * NH)
#define O_G3B   (8 * NH)   // G3B,UB contiguous (selector GEMM output)
#define O_UB    (9 * NH)
#define O_U     (10 * NH)
#define O_PAIRA (11 * NH)  // 3*NH
#define O_PAIRB (14 * NH)  // 3*NH
#define O_PROJ  (17 * NH)
#define O_H1P   (18 * NH)  // H1P,H2P contiguous
#define O_H2P   (19 * NH)
#define O_VN    (20 * NH)
#define O_UEMD  (21 * NH)
#define O_Z1    (22 * NH)  // bf16: Z1 (NH) then Z2 (NH)
#define O_TAIL  (23 * NH)
#define O_COLS1 (O_TAIL)
#define O_COLS2 (O_COLS1 + (size_t)NN * MAXNZ)
#define O_CNT1  (O_COLS2 + (size_t)NN * MAXNZ)
#define O_CNT2  (O_CNT1 + NN)
#define O_R1    (O_CNT2 + NN)
#define O_R2    (O_R1 + NN)
#define O_BR    (O_R2 + NN)
#define O_BC    (O_BR + NN)
#define O_SII   (O_BC + NN)
#define O_LSEM  (O_SII + NN)
#define O_LG    (O_LSEM + NN)

__device__ __forceinline__ float* scr(size_t off) { return g_scratch + off; }
__device__ __forceinline__ int* scri(size_t off) { return (int*)(g_scratch + off); }

// ---------------------------------------------------------------------------
// PTX helpers
// ---------------------------------------------------------------------------
__device__ __forceinline__ uint32_t f2tf(float f) {
    uint32_t r;
    asm("cvt.rna.tf32.f32 %0, %1;" : "=r"(r) : "f"(f));
    return r;
}
__device__ __forceinline__ void mma1688tf(float c[4], const uint32_t a[4], const uint32_t b[2]) {
    asm volatile(
        "mma.sync.aligned.m16n8k8.row.col.f32.tf32.tf32.f32 "
        "{%0,%1,%2,%3}, {%4,%5,%6,%7}, {%8,%9}, {%0,%1,%2,%3};\n"
        : "+f"(c[0]), "+f"(c[1]), "+f"(c[2]), "+f"(c[3])
        : "r"(a[0]), "r"(a[1]), "r"(a[2]), "r"(a[3]), "r"(b[0]), "r"(b[1]));
}
__device__ __forceinline__ void mma16816v(float c[4], const uint32_t a[4], const uint32_t b[2]) {
    asm volatile(
        "mma.sync.aligned.m16n8k16.row.col.f32.bf16.bf16.f32 "
        "{%0,%1,%2,%3}, {%4,%5,%6,%7}, {%8,%9}, {%0,%1,%2,%3};\n"
        : "+f"(c[0]), "+f"(c[1]), "+f"(c[2]), "+f"(c[3])
        : "r"(a[0]), "r"(a[1]), "r"(a[2]), "r"(a[3]), "r"(b[0]), "r"(b[1]));
}
__device__ __forceinline__ uint32_t s2u(const void* p) {
    return (uint32_t)__cvta_generic_to_shared(p);
}
__device__ __forceinline__ void cpasync16(uint32_t dst, const void* src) {
    asm volatile("cp.async.cg.shared.global [%0], [%1], 16;" :: "r"(dst), "l"(src));
}
#define CP_COMMIT() asm volatile("cp.async.commit_group;")
#define CP_WAIT1()  asm volatile("cp.async.wait_group 1;")
__device__ __forceinline__ void ldsm_x4(uint32_t r[4], uint32_t addr) {
    asm volatile("ldmatrix.sync.aligned.m8n8.x4.shared.b16 {%0,%1,%2,%3}, [%4];"
                 : "=r"(r[0]), "=r"(r[1]), "=r"(r[2]), "=r"(r[3]) : "r"(addr));
}
__device__ __forceinline__ void ldsm_x2(uint32_t r[2], uint32_t addr) {
    asm volatile("ldmatrix.sync.aligned.m8n8.x2.shared.b16 {%0,%1}, [%2];"
                 : "=r"(r[0]), "=r"(r[1]) : "r"(addr));
}

// ---------------------------------------------------------------------------

__global__ void k_zero4() {
    int i = blockIdx.x * blockDim.x + threadIdx.x;
    if (i < NN) {
        scr(O_R1)[i] = 0.f; scr(O_R2)[i] = 0.f;
        scr(O_BR)[i] = 0.f; scr(O_BC)[i] = 0.f;
    }
}

__global__ void k_extract(const float* __restrict__ adj, size_t colsOff, size_t cntOff) {
    int* cols = scri(colsOff);
    int* cnts = scri(cntOff);
    int row = blockIdx.x;
    __shared__ int scnt;
    if (threadIdx.x == 0) scnt = 0;
    __syncthreads();
    const float4* a4 = (const float4*)(adj + (size_t)row * NN);
    for (int i = threadIdx.x; i < NN / 4; i += blockDim.x) {
        float4 v = a4[i];
        int base = i * 4;
        if (v.x != 0.f) { int s = atomicAdd(&scnt, 1); if (s < MAXNZ) cols[(size_t)row * MAXNZ + s] = base + 0; }
        if (v.y != 0.f) { int s = atomicAdd(&scnt, 1); if (s < MAXNZ) cols[(size_t)row * MAXNZ + s] = base + 1; }
        if (v.z != 0.f) { int s = atomicAdd(&scnt, 1); if (s < MAXNZ) cols[(size_t)row * MAXNZ + s] = base + 2; }
        if (v.w != 0.f) { int s = atomicAdd(&scnt, 1); if (s < MAXNZ) cols[(size_t)row * MAXNZ + s] = base + 3; }
    }
    __syncthreads();
    if (threadIdx.x == 0) cnts[row] = scnt > MAXNZ ? MAXNZ : scnt;
}

// Paired SpMM: one gather, two feature matrices.
__global__ void k_spmm2(size_t colsOff, size_t cntOff,
                        size_t X1Off, size_t X2Off,
                        const float* __restrict__ bias1, const float* __restrict__ bias2,
                        size_t out1Off, size_t out2Off) {
    const int* cols = scri(colsOff);
    const float* X1 = scr(X1Off);
    const float* X2 = scr(X2Off);
    __shared__ int sc[MAXNZ];
    int row = blockIdx.x;
    int cnt = scri(cntOff)[row];
    if (threadIdx.x < cnt) sc[threadIdx.x] = cols[(size_t)row * MAXNZ + threadIdx.x];
    __syncthreads();
    float a1 = 0.f, a2 = 0.f;
    for (int j = 0; j < cnt; j++) {
        size_t base = (size_t)sc[j] * HH + threadIdx.x;
        a1 += X1[base];
        a2 += X2[base];
    }
    float v = cnt > 0 ? (1.0f / (float)cnt) : 0.0f;
    scr(out1Off)[(size_t)row * HH + threadIdx.x] = v * a1 + bias1[threadIdx.x];
    scr(out2Off)[(size_t)row * HH + threadIdx.x] = v * a2 + bias2[threadIdx.x];
}

// ---------------------------------------------------------------------------
// tf32 GEMM core (register-staged double buffer). Macro-free struct reuse via
// device inline: A provided per-row through a functor-style pointer resolve.
// Variants: plain (single A), dualA (two external A), sel (scratch A + region
// weight select).
// ---------------------------------------------------------------------------
struct GemmSmem {
    uint32_t As[2][128][20];
    uint32_t Bs[2][16][136];
};

template <typename AF, typename BF>
__device__ __forceinline__ void gemm_core(AF arow, BF bsel, const float* bias0,
                                          const float* bias1, size_t COff,
                                          int K, int relu) {
    __shared__ GemmSmem sm;
    float* C = scr(COff);
    int tid = threadIdx.x;
    int bn = blockIdx.x * 128, bm = blockIdx.y * 128;
    const float* B = bsel(bm);
    const float* bias = (bm >= NN) ? bias1 : bias0;
    int wid = tid >> 5, lane = tid & 31;
    int warpM = wid >> 2, warpN = wid & 3;
    int g = lane >> 2, tig = lane & 3;

    int rA0 = tid >> 2, kqA0 = (tid & 3) * 4;
    int rA1 = (tid + 256) >> 2, kqA1 = ((tid + 256) & 3) * 4;
    int kB0 = tid >> 5, nB0 = (tid & 31) * 4;
    int kB1 = (tid + 256) >> 5, nB1 = ((tid + 256) & 31) * 4;

    float4 ra0, ra1, rb0, rb1;
    auto loadT = [&](int t) {
        int k0 = t * 16;
        ra0 = *(const float4*)(arow(bm + rA0) + k0 + kqA0);
        ra1 = *(const float4*)(arow(bm + rA1) + k0 + kqA1);
        rb0 = *(const float4*)(B + (size_t)(k0 + kB0) * HH + bn + nB0);
        rb1 = *(const float4*)(B + (size_t)(k0 + kB1) * HH + bn + nB1);
    };
    auto storeT = [&](int buf) {
        uint4 u0 = {f2tf(ra0.x), f2tf(ra0.y), f2tf(ra0.z), f2tf(ra0.w)};
        uint4 u1 = {f2tf(ra1.x), f2tf(ra1.y), f2tf(ra1.z), f2tf(ra1.w)};
        uint4 v0 = {f2tf(rb0.x), f2tf(rb0.y), f2tf(rb0.z), f2tf(rb0.w)};
        uint4 v1 = {f2tf(rb1.x), f2tf(rb1.y), f2tf(rb1.z), f2tf(rb1.w)};
        *(uint4*)&sm.As[buf][rA0][kqA0] = u0;
        *(uint4*)&sm.As[buf][rA1][kqA1] = u1;
        *(uint4*)&sm.Bs[buf][kB0][nB0] = v0;
        *(uint4*)&sm.Bs[buf][kB1][nB1] = v1;
    };

    float acc[4][4][4];
#pragma unroll
    for (int i = 0; i < 4; i++)
#pragma unroll
        for (int j = 0; j < 4; j++)
#pragma unroll
            for (int q = 0; q < 4; q++) acc[i][j][q] = 0.f;

    int T = K / 16;
    loadT(0);
    storeT(0);
    __syncthreads();
    for (int t = 0; t < T; t++) {
        int buf = t & 1;
        if (t + 1 < T) loadT(t + 1);
#pragma unroll
        for (int kk = 0; kk < 16; kk += 8) {
            uint32_t a[4][4], b[4][2];
#pragma unroll
            for (int mt = 0; mt < 4; mt++) {
                int r0 = warpM * 64 + mt * 16;
                a[mt][0] = sm.As[buf][r0 + g][kk + tig];
                a[mt][1] = sm.As[buf][r0 + 8 + g][kk + tig];
                a[mt][2] = sm.As[buf][r0 + g][kk + tig + 4];
                a[mt][3] = sm.As[buf][r0 + 8 + g][kk + tig + 4];
            }
#pragma unroll
            for (int nt = 0; nt < 4; nt++) {
                int c0 = warpN * 32 + nt * 8;
                b[nt][0] = sm.Bs[buf][kk + tig][c0 + g];
                b[nt][1] = sm.Bs[buf][kk + tig + 4][c0 + g];
            }
#pragma unroll
            for (int mt = 0; mt < 4; mt++)
#pragma unroll
                for (int nt = 0; nt < 4; nt++) mma1688tf(acc[mt][nt], a[mt], b[nt]);
        }
        if (t + 1 < T) storeT((t + 1) & 1);
        __syncthreads();
    }

#pragma unroll
    for (int mt = 0; mt < 4; mt++) {
        int row0 = bm + warpM * 64 + mt * 16 + g;
#pragma unroll
        for (int nt = 0; nt < 4; nt++) {
            int col = bn + warpN * 32 + nt * 8 + tig * 2;
            float bb0 = bias ? bias[col] : 0.f;
            float bb1 = bias ? bias[col + 1] : 0.f;
            float v0 = acc[mt][nt][0] + bb0, v1 = acc[mt][nt][1] + bb1;
            float v2 = acc[mt][nt][2] + bb0, v3 = acc[mt][nt][3] + bb1;
            if (relu) {
                v0 = fmaxf(v0, 0.f); v1 = fmaxf(v1, 0.f);
                v2 = fmaxf(v2, 0.f); v3 = fmaxf(v3, 0.f);
            }
            float2 p0 = {v0, v1}, p1 = {v2, v3};
            *(float2*)(C + (size_t)row0 * HH + col) = p0;
            *(float2*)(C + (size_t)(row0 + 8) * HH + col) = p1;
        }
    }
}

// Single external-or-scratch A, single weight.
__global__ __launch_bounds__(256) void k_gemm_tc(const float* Aext, size_t AOff,
                                                 const float* __restrict__ B,
                                                 const float* __restrict__ bias,
                                                 size_t COff, int K, int relu) {
    const float* Abase = Aext ? Aext : scr(AOff);
    gemm_core([&](int m) { return Abase + (size_t)m * K; },
              [&](int) { return B; }, bias, bias, COff, K, relu);
}

// Dual external A (x1 rows [0,NN), x2 rows [NN,2NN)), single weight.
__global__ __launch_bounds__(256) void k_gemm_dualA(const float* A0, const float* A1,
                                                    const float* __restrict__ B,
                                                    size_t COff, int K) {
    gemm_core([&](int m) {
                  return m < NN ? A0 + (size_t)m * K : A1 + (size_t)(m - NN) * K;
              },
              [&](int) { return B; }, nullptr, nullptr, COff, K, 0);
}

// Scratch A (contiguous multi-region), weight/bias selected by bm >= NN.
__global__ __launch_bounds__(256) void k_gemm_sel(size_t AOff,
                                                  const float* __restrict__ B0,
                                                  const float* __restrict__ B1,
                                                  const float* bias0, const float* bias1,
                                                  size_t COff, int K, int relu) {
    const float* Abase = scr(AOff);
    gemm_core([&](int m) { return Abase + (size_t)m * K; },
              [&](int bm) { return bm >= NN ? B1 : B0; },
              bias0, bias1, COff, K, relu);
}

// Row l2-normalize (simple).
__global__ void k_l2norm(size_t XOff, size_t outOff) {
    const float* X = scr(XOff);
    float* out = scr(outOff);
    int row = blockIdx.x, t = threadIdx.x;
    float x = X[(size_t)row * HH + t];
    float s = x * x;
#pragma unroll
    for (int o = 16; o; o >>= 1) s += __shfl_xor_sync(0xffffffffu, s, o);
    __shared__ float red[8];
    if ((t & 31) == 0) red[t >> 5] = s;
    __syncthreads();
    float tot = 0.f;
#pragma unroll
    for (int i = 0; i < 8; i++) tot += red[i];
    float inv = 1.0f / fmaxf(sqrtf(tot), 1e-12f);
    out[(size_t)row * HH + t] = x * inv;
}

// Batched l2norm over the 3NN-row MLP output:
//   rows [0,NN)    -> PROJ (fp32 only)
//   rows [NN,3NN)  -> H1P/H2P (fp32) + Z1/Z2 (bf16)
__global__ void k_l2norm3(size_t XOff) {
    const float* X = scr(XOff);
    int row = blockIdx.x, t = threadIdx.x;
    float x = X[(size_t)row * HH + t];
    float s = x * x;
#pragma unroll
    for (int o = 16; o; o >>= 1) s += __shfl_xor_sync(0xffffffffu, s, o);
    __shared__ float red[8];
    if ((t & 31) == 0) red[t >> 5] = s;
    __syncthreads();
    float tot = 0.f;
#pragma unroll
    for (int i = 0; i < 8; i++) tot += red[i];
    float inv = 1.0f / fmaxf(sqrtf(tot), 1e-12f);
    float y = x * inv;
    if (row < NN) {
        scr(O_PROJ)[(size_t)row * HH + t] = y;
    } else {
        size_t r2 = (size_t)(row - NN);
        scr(O_H1P)[r2 * HH + t] = y;
        ((__nv_bfloat16*)scr(O_Z1))[r2 * HH + t] = __float2bfloat16(y);
    }
}

// ---------------------------------------------------------------------------
// Fused exp-gram, cp.async double buffer + ldmatrix fragments.
// ---------------------------------------------------------------------------
__global__ __launch_bounds__(256) void k_gram(size_t AOff, size_t BOff,
                                              size_t rowOff, long long colOff,
                                              int symmetric) {
    int bx = blockIdx.x, by = blockIdx.y;
    if (symmetric && bx < by) return;
    const __nv_bfloat16* A = (const __nv_bfloat16*)scr(O_Z1) + AOff;
    const __nv_bfloat16* Bm = (const __nv_bfloat16*)scr(O_Z1) + BOff;
    float* rowSum = scr(rowOff);
    __shared__ __nv_bfloat16 As[2][128][40];
    __shared__ __nv_bfloat16 Bs[2][128][40];
    int tid = threadIdx.x;
    int wid = tid >> 5, lane = tid & 31;
    int warpM = wid >> 2, warpN = wid & 3;
    int g = lane >> 2, tig = lane & 3;
    const int rowBase = by * 128, colBase = bx * 128;

    int rL0 = tid >> 2, kL0 = (tid & 3) * 8;
    int rL1 = (tid + 256) >> 2, kL1 = ((tid + 256) & 3) * 8;

    auto prefetch = [&](int t, int buf) {
        int k0 = t * 32;
        cpasync16(s2u(&As[buf][rL0][kL0]), A + (size_t)(rowBase + rL0) * HH + k0 + kL0);
        cpasync16(s2u(&As[buf][rL1][kL1]), A + (size_t)(rowBase + rL1) * HH + k0 + kL1);
        cpasync16(s2u(&Bs[buf][rL0][kL0]), Bm + (size_t)(colBase + rL0) * HH + k0 + kL0);
        cpasync16(s2u(&Bs[buf][rL1][kL1]), Bm + (size_t)(colBase + rL1) * HH + k0 + kL1);
    };

    float acc[4][4][4];
#pragma unroll
    for (int a = 0; a < 4; a++)
#pragma unroll
        for (int b = 0; b < 4; b++)
#pragma unroll
            for (int q = 0; q < 4; q++) acc[a][b][q] = 0.f;

    const int T = HH / 32;  // 8
    prefetch(0, 0);
    CP_COMMIT();
    for (int t = 0; t < T; t++) {
        int buf = t & 1;
        if (t + 1 < T) prefetch(t + 1, (t + 1) & 1);
        CP_COMMIT();
        CP_WAIT1();
        __syncthreads();
        uint32_t asb = s2u(&As[buf][0][0]);
        uint32_t bsb = s2u(&Bs[buf][0][0]);
#pragma unroll
        for (int kk = 0; kk < 32; kk += 16) {
            uint32_t af[4][4], bf[4][2];
#pragma unroll
            for (int mt = 0; mt < 4; mt++) {
                int row = warpM * 64 + mt * 16 + (lane & 15);
                int col = kk + ((lane >> 4) << 3);
                ldsm_x4(af[mt], asb + (row * 40 + col) * 2);
            }
#pragma unroll
            for (int nt = 0; nt < 4; nt++) {
                int row = warpN * 32 + nt * 8 + (lane & 7);
                int col = kk + (((lane >> 3) & 1) << 3);
                ldsm_x2(bf[nt], bsb + (row * 40 + col) * 2);
            }
#pragma unroll
            for (int mt = 0; mt < 4; mt++)
#pragma unroll
                for (int nt = 0; nt < 4; nt++) mma16816v(acc[mt][nt], af[mt], bf[nt]);
        }
        __syncthreads();
    }

    float rs[4][2], cs[4][2];
#pragma unroll
    for (int i = 0; i < 4; i++) { rs[i][0] = rs[i][1] = 0.f; cs[i][0] = cs[i][1] = 0.f; }
#pragma unroll
    for (int mt = 0; mt < 4; mt++)
#pragma unroll
        for (int nt = 0; nt < 4; nt++) {
            float e0 = exp2f(acc[mt][nt][0] * EXPC);
            float e1 = exp2f(acc[mt][nt][1] * EXPC);
            float e2 = exp2f(acc[mt][nt][2] * EXPC);
            float e3 = exp2f(acc[mt][nt][3] * EXPC);
            rs[mt][0] += e0 + e1; rs[mt][1] += e2 + e3;
            cs[nt][0] += e0 + e2; cs[nt][1] += e1 + e3;
        }
#pragma unroll
    for (int mt = 0; mt < 4; mt++)
#pragma unroll
        for (int h = 0; h < 2; h++) {
            float v = rs[mt][h];
            v += __shfl_xor_sync(0xffffffffu, v, 1);
            v += __shfl_xor_sync(0xffffffffu, v, 2);
            if (tig == 0) {
                int r = rowBase + warpM * 64 + mt * 16 + g + h * 8;
                atomicAdd(&rowSum[r], v);
            }
        }
    bool wantCol = symmetric ? (bx != by) : (colOff >= 0);
    if (wantCol) {
        float* dst = symmetric ? rowSum : scr((size_t)colOff);
#pragma unroll
        for (int nt = 0; nt < 4; nt++)
#pragma unroll
            for (int h = 0; h < 2; h++) {
                float v = cs[nt][h];
                v += __shfl_xor_sync(0xffffffffu, v, 4);
                v += __shfl_xor_sync(0xffffffffu, v, 8);
                v += __shfl_xor_sync(0xffffffffu, v, 16);
                if (g == 0) {
                    int c = colBase + warpN * 32 + nt * 8 + tig * 2 + h;
                    atomicAdd(&dst[c], v);
                }
            }
    }
}

// sii[i] = dot(A_i, B_i) fp32
__global__ void k_sii(size_t AOff, size_t BOff, size_t sOff) {
    const float* A = scr(AOff);
    const float* B = scr(BOff);
    int w = threadIdx.x >> 5, lane = threadIdx.x & 31;
    int row = blockIdx.x * 8 + w;
    const float* a = A + (size_t)row * HH + lane * 8;
    const float* b = B + (size_t)row * HH + lane * 8;
    float4 a0 = *(const float4*)a, a1 = *(const float4*)(a + 4);
    float4 b0 = *(const float4*)b, b1 = *(const float4*)(b + 4);
    float s = a0.x * b0.x + a0.y * b0.y + a0.z * b0.z + a0.w * b0.w +
              a1.x * b1.x + a1.y * b1.y + a1.z * b1.z + a1.w * b1.w;
#pragma unroll
    for (int o = 16; o; o >>= 1) s += __shfl_xor_sync(0xffffffffu, s, o);
    if (lane == 0) scr(sOff)[row] = s;
}

__global__ void k_semi() {
    int i = blockIdx.x * blockDim.x + threadIdx.x;
    if (i >= NN) return;
    float dl = scr(O_SII)[i] * 2.0f;
    float l1 = logf(scr(O_R1)[i] + scr(O_BR)[i] - EDIAG) - dl;
    float l2 = logf(scr(O_R2)[i] + scr(O_BC)[i] - EDIAG) - dl;
    scr(O_LSEM)[i] = 0.5f * (l1 + l2);
}

__global__ void k_contrast(const int* __restrict__ nbi, const int* __restrict__ ngi) {
    const float* proj = scr(O_PROJ);
    const float* uemd = scr(O_UEMD);
    const float* vn = scr(O_VN);
    int w = threadIdx.x >> 5, lane = threadIdx.x & 31;
    int n = blockIdx.x * 8 + w;
    float p[8], v[8];
    {
        const float4* pp = (const float4*)(proj + (size_t)n * HH + lane * 8);
        ((float4*)p)[0] = pp[0]; ((float4*)p)[1] = pp[1];
        const float4* vv = (const float4*)(vn + (size_t)n * HH + lane * 8);
        ((float4*)v)[0] = vv[0]; ((float4*)v)[1] = vv[1];
    }
    float posd[SS];
    float negsum = 0.f;
#pragma unroll
    for (int s = 0; s < SS; s++) {
        int nb = nbi[n * SS + s];
        const float4* uu = (const float4*)(uemd + (size_t)nb * HH + lane * 8);
        float u[8]; ((float4*)u)[0] = uu[0]; ((float4*)u)[1] = uu[1];
        float d = 0.f;
#pragma unroll
        for (int k = 0; k < 8; k++) d += p[k] * u[k];
#pragma unroll
        for (int o = 16; o; o >>= 1) d += __shfl_xor_sync(0xffffffffu, d, o);
        posd[s] = d;
        int ng = ngi[n * SS + s];
        const float4* qq = (const float4*)(vn + (size_t)ng * HH + lane * 8);
        float q[8]; ((float4*)q)[0] = qq[0]; ((float4*)q)[1] = qq[1];
        float d2 = 0.f;
#pragma unroll
        for (int k = 0; k < 8; k++) d2 += v[k] * q[k];
#pragma unroll
        for (int o = 16; o; o >>= 1) d2 += __shfl_xor_sync(0xffffffffu, d2, o);
        negsum += exp2f(d2 * EXPC);
    }
    float ns = 0.f, ps = 0.f;
#pragma unroll
    for (int s = 0; s < SS; s++) {
        float pos = exp2f(posd[s] * EXPC);
        ns += logf(pos + negsum);
        ps += posd[s] * 2.0f;
    }
    if (lane == 0) scr(O_LG)[n] = ns - ps;
}

__global__ void k_reduce(float* __restrict__ out) {
    __shared__ float s1[1024], s2[1024];
    int t = threadIdx.x;
    float a = 0.f, b = 0.f;
    for (int i = t; i < NN; i += 1024) { a += scr(O_LG)[i]; b += scr(O_LSEM)[i]; }
    s1[t] = a; s2[t] = b;
    __syncthreads();
    for (int s = 512; s > 0; s >>= 1) {
        if (t < s) { s1[t] += s1[t + s]; s2[t] += s2[t + s]; }
        __syncthreads();
    }
    if (t == 0) {
        float gacl = s1[0] / ((float)NN * (float)SS);
        float sem = s2[0] / (float)NN;
        out[0] = gacl + 0.6f * sem;
        out[1] = gacl;
        out[2] = sem;
    }
}

// Alignment-agnostic copy (dst = out + 3 is NOT 16B aligned).
__global__ void k_copy(size_t srcOff, float* __restrict__ dst, size_t n4) {
    size_t i = (size_t)blockIdx.x * blockDim.x + threadIdx.x;
    if (i < n4) {
        float4 v = ((const float4*)scr(srcOff))[i];
        float* d = dst + i * 4;
        d[0] = v.x; d[1] = v.y; d[2] = v.z; d[3] = v.w;
    }
}

// ---------------------------------------------------------------------------
extern "C" void kernel_launch(void* const* d_in, const int* in_sizes, int n_in,
                              void* d_out, int out_size) {
    const float* adj1 = (const float*)d_in[0];
    const float* adj2 = (const float*)d_in[1];
    const float* x1 = (const float*)d_in[2];
    const float* x2 = (const float*)d_in[3];
    const int* nbi = (const int*)d_in[4];
    const int* ngi = (const int*)d_in[5];
    const float* W1 = (const float*)d_in[6];
    const float* b1 = (const float*)d_in[7];
    const float* W2 = (const float*)d_in[8];
    const float* b2 = (const float*)d_in[9];
    const float* tW1 = (const float*)d_in[10];
    const float* tb1 = (const float*)d_in[11];
    const float* tW2 = (const float*)d_in[12];
    const float* tb2 = (const float*)d_in[13];
    const float* pW0 = (const float*)d_in[14];
    const float* pB0 = (const float*)d_in[15];
    const float* pW1 = (const float*)d_in[16];
    const float* pB1 = (const float*)d_in[17];
    const float* pW2 = (const float*)d_in[18];
    const float* pB2 = (const float*)d_in[19];
    const float* sW0 = (const float*)d_in[20];
    const float* sB0 = (const float*)d_in[21];
    const float* sW1 = (const float*)d_in[22];
    const float* sB1 = (const float*)d_in[23];
    const float* sW2 = (const float*)d_in[24];
    const float* sB2 = (const float*)d_in[25];

    float* out = (float*)d_out;
    size_t h3_off = (size_t)out_size - NH;

    dim3 gemmGrid(2, NN / 128);
    dim3 gemmGrid2(2, 2 * NN / 128);
    dim3 gemmGrid3(2, 3 * NN / 128);
    dim3 gramGrid(128, 128);

    k_zero4<<<NN / 256, 256>>>();
    k_extract<<<NN, 256>>>(adj1, O_COLS1, O_CNT1);
    k_extract<<<NN, 256>>>(adj2, O_COLS2, O_CNT2);

    // stage A: [x1;x2] @ W1 (batched), x1 @ tW1
    k_gemm_dualA<<<gemmGrid2, 256>>>(x1, x2, W1, O_P1, DIN);
    k_gemm_tc<<<gemmGrid, 256>>>(x1, 0, tW1, nullptr, O_T1, DIN, 0);

    // paired graph convs
    k_spmm2<<<NN, 256>>>(O_COLS1, O_CNT1, O_P1, O_P2, b1, b1, O_H1, O_H2);
    k_spmm2<<<NN, 256>>>(O_COLS2, O_CNT2, O_P1, O_T1, b1, tb1, O_G3A, O_UA);

    // [G3A;UA] @ {W2|tW2} (batched selector)
    k_gemm_sel<<<gemmGrid2, 256>>>(O_G3A, W2, tW2, nullptr, nullptr, O_G3B, HH, 0);

    k_spmm2<<<NN, 256>>>(O_COLS2, O_CNT2, O_G3B, O_UB, b2, tb2, O_H3, O_U);

    k_l2norm<<<NN, 256>>>(O_U, O_UEMD);
    k_l2norm<<<NN, 256>>>(O_H3, O_VN);

    // batched MLP on [h3; h1; h2]: region 0 -> proj weights, regions 1,2 -> sem
    k_gemm_sel<<<gemmGrid3, 256>>>(O_H3, pW0, sW0, pB0, sB0, O_PAIRA, HH, 1);
    k_gemm_sel<<<gemmGrid3, 256>>>(O_PAIRA, pW1, sW1, pB1, sB1, O_PAIRB, HH, 1);
    k_gemm_sel<<<gemmGrid3, 256>>>(O_PAIRB, pW2, sW2, pB2, sB2, O_PAIRA, HH, 0);
    k_l2norm3<<<3 * NN, 256>>>(O_PAIRA);

    // fused exp-gram row/col sums
    k_gram<<<gramGrid, 256>>>(0, 0, O_R1, -1, 1);
    k_gram<<<gramGrid, 256>>>(NH, NH, O_R2, -1, 1);
    k_gram<<<gramGrid, 256>>>(0, NH, O_BR, (long long)O_BC, 0);

    k_sii<<<NN / 8, 256>>>(O_H1P, O_H2P, O_SII);
    k_semi<<<NN / 256, 256>>>();
    k_contrast<<<NN / 8, 256>>>(nbi, ngi);

    k_reduce<<<1, 1024>>>(out);
    k_copy<<<(unsigned)((NH / 4 + 255) / 256), 256>>>(O_H3, out + h3_off, NH / 4);
}

// round 12
// speedup vs baseline: 1.5445x; 1.0438x over previous
#include <cuda_runtime.h>
#include <cuda_bf16.h>
#include <cstdint>
#include <cstddef>

#define NN 16384
#define HH 256
#define DIN 512
#define SS 8
#define MAXNZ 64
#define NH 4194304UL  // NN*HH floats

#define EXPC 2.8853900817779268f   // log2(e)/tau, tau=0.5
#define EDIAG 7.389056098930650f   // exp(2)

// ---------------------------------------------------------------------------
// Scratch
// ---------------------------------------------------------------------------
__device__ float g_scratch[23 * NH + 2 * (NN * MAXNZ) + 2 * NN + 8 * NN];

#define O_P1    (0 * NH)
#define O_P2    (1 * NH)
#define O_T1    (2 * NH)
#define O_H3    (3 * NH)   // H3,H1,H2 contiguous (batched MLP input)
#define O_H1    (4 * NH)
#define O_H2    (5 * NH)
#define O_G3A   (6 * NH)   // G3A,UA contiguous
#define O_UA    (7 * NH)
#define O_G3B   (8 * NH)   // G3B,UB contiguous
#define O_UB    (9 * NH)
#define O_U     (10 * NH)
#define O_PAIRA (11 * NH)  // 3*NH
#define O_PAIRB (14 * NH)  // 3*NH
#define O_PROJ  (17 * NH)
#define O_H1P   (18 * NH)  // H1P,H2P contiguous
#define O_H2P   (19 * NH)
#define O_VN    (20 * NH)
#define O_UEMD  (21 * NH)
#define O_Z1    (22 * NH)  // bf16: Z1 (NH) then Z2 (NH)
#define O_TAIL  (23 * NH)
#define O_COLS1 (O_TAIL)
#define O_COLS2 (O_COLS1 + (size_t)NN * MAXNZ)
#define O_CNT1  (O_COLS2 + (size_t)NN * MAXNZ)
#define O_CNT2  (O_CNT1 + NN)
#define O_R1    (O_CNT2 + NN)
#define O_R2    (O_R1 + NN)
#define O_BR    (O_R2 + NN)
#define O_BC    (O_BR + NN)
#define O_SII   (O_BC + NN)
#define O_LSEM  (O_SII + NN)
#define O_LG    (O_LSEM + NN)

__device__ __forceinline__ float* scr(size_t off) { return g_scratch + off; }
__device__ __forceinline__ int* scri(size_t off) { return (int*)(g_scratch + off); }

// ---------------------------------------------------------------------------
// PTX helpers
// ---------------------------------------------------------------------------
__device__ __forceinline__ uint32_t f2tf(float f) {
    uint32_t r;
    asm("cvt.rna.tf32.f32 %0, %1;" : "=r"(r) : "f"(f));
    return r;
}
__device__ __forceinline__ void mma1688tf(float c[4], const uint32_t a[4], const uint32_t b[2]) {
    asm volatile(
        "mma.sync.aligned.m16n8k8.row.col.f32.tf32.tf32.f32 "
        "{%0,%1,%2,%3}, {%4,%5,%6,%7}, {%8,%9}, {%0,%1,%2,%3};\n"
        : "+f"(c[0]), "+f"(c[1]), "+f"(c[2]), "+f"(c[3])
        : "r"(a[0]), "r"(a[1]), "r"(a[2]), "r"(a[3]), "r"(b[0]), "r"(b[1]));
}
__device__ __forceinline__ void mma16816v(float c[4], const uint32_t a[4], const uint32_t b[2]) {
    asm volatile(
        "mma.sync.aligned.m16n8k16.row.col.f32.bf16.bf16.f32 "
        "{%0,%1,%2,%3}, {%4,%5,%6,%7}, {%8,%9}, {%0,%1,%2,%3};\n"
        : "+f"(c[0]), "+f"(c[1]), "+f"(c[2]), "+f"(c[3])
        : "r"(a[0]), "r"(a[1]), "r"(a[2]), "r"(a[3]), "r"(b[0]), "r"(b[1]));
}
__device__ __forceinline__ uint32_t s2u(const void* p) {
    return (uint32_t)__cvta_generic_to_shared(p);
}
__device__ __forceinline__ void cpasync16(uint32_t dst, const void* src) {
    asm volatile("cp.async.cg.shared.global [%0], [%1], 16;" :: "r"(dst), "l"(src));
}
#define CP_COMMIT() asm volatile("cp.async.commit_group;")
#define CP_WAIT1()  asm volatile("cp.async.wait_group 1;")
__device__ __forceinline__ void ldsm_x4(uint32_t r[4], uint32_t addr) {
    asm volatile("ldmatrix.sync.aligned.m8n8.x4.shared.b16 {%0,%1,%2,%3}, [%4];"
                 : "=r"(r[0]), "=r"(r[1]), "=r"(r[2]), "=r"(r[3]) : "r"(addr));
}
__device__ __forceinline__ void ldsm_x2(uint32_t r[2], uint32_t addr) {
    asm volatile("ldmatrix.sync.aligned.m8n8.x2.shared.b16 {%0,%1}, [%2];"
                 : "=r"(r[0]), "=r"(r[1]) : "r"(addr));
}

// ---------------------------------------------------------------------------

__global__ void k_zero4() {
    int i = blockIdx.x * blockDim.x + threadIdx.x;
    if (i < NN) {
        scr(O_R1)[i] = 0.f; scr(O_R2)[i] = 0.f;
        scr(O_BR)[i] = 0.f; scr(O_BC)[i] = 0.f;
    }
}

__global__ void k_extract(const float* __restrict__ adj, size_t colsOff, size_t cntOff) {
    int* cols = scri(colsOff);
    int* cnts = scri(cntOff);
    int row = blockIdx.x;
    __shared__ int scnt;
    if (threadIdx.x == 0) scnt = 0;
    __syncthreads();
    const float4* a4 = (const float4*)(adj + (size_t)row * NN);
    for (int i = threadIdx.x; i < NN / 4; i += blockDim.x) {
        float4 v = a4[i];
        int base = i * 4;
        if (v.x != 0.f) { int s = atomicAdd(&scnt, 1); if (s < MAXNZ) cols[(size_t)row * MAXNZ + s] = base + 0; }
        if (v.y != 0.f) { int s = atomicAdd(&scnt, 1); if (s < MAXNZ) cols[(size_t)row * MAXNZ + s] = base + 1; }
        if (v.z != 0.f) { int s = atomicAdd(&scnt, 1); if (s < MAXNZ) cols[(size_t)row * MAXNZ + s] = base + 2; }
        if (v.w != 0.f) { int s = atomicAdd(&scnt, 1); if (s < MAXNZ) cols[(size_t)row * MAXNZ + s] = base + 3; }
    }
    __syncthreads();
    if (threadIdx.x == 0) cnts[row] = scnt > MAXNZ ? MAXNZ : scnt;
}

// Paired SpMM: one gather, two feature matrices.
__global__ void k_spmm2(size_t colsOff, size_t cntOff,
                        size_t X1Off, size_t X2Off,
                        const float* __restrict__ bias1, const float* __restrict__ bias2,
                        size_t out1Off, size_t out2Off) {
    const int* cols = scri(colsOff);
    const float* X1 = scr(X1Off);
    const float* X2 = scr(X2Off);
    __shared__ int sc[MAXNZ];
    int row = blockIdx.x;
    int cnt = scri(cntOff)[row];
    if (threadIdx.x < cnt) sc[threadIdx.x] = cols[(size_t)row * MAXNZ + threadIdx.x];
    __syncthreads();
    float a1 = 0.f, a2 = 0.f;
#pragma unroll 4
    for (int j = 0; j < cnt; j++) {
        size_t base = (size_t)sc[j] * HH + threadIdx.x;
        a1 += X1[base];
        a2 += X2[base];
    }
    float v = cnt > 0 ? (1.0f / (float)cnt) : 0.0f;
    scr(out1Off)[(size_t)row * HH + threadIdx.x] = v * a1 + bias1[threadIdx.x];
    scr(out2Off)[(size_t)row * HH + threadIdx.x] = v * a2 + bias2[threadIdx.x];
}

// ---------------------------------------------------------------------------
// tf32 GEMM core: register-staged double buffer + ldmatrix A-fragments.
// ---------------------------------------------------------------------------
struct GemmSmem {
    uint32_t As[2][128][20];
    uint32_t Bs[2][16][136];
};

template <typename AF, typename BF>
__device__ __forceinline__ void gemm_core(AF arow, BF bsel, const float* bias0,
                                          const float* bias1, size_t COff,
                                          int K, int relu) {
    __shared__ GemmSmem sm;
    float* C = scr(COff);
    int tid = threadIdx.x;
    int bn = blockIdx.x * 128, bm = blockIdx.y * 128;
    const float* B = bsel(bm);
    const float* bias = (bm >= NN) ? bias1 : bias0;
    int wid = tid >> 5, lane = tid & 31;
    int warpM = wid >> 2, warpN = wid & 3;
    int g = lane >> 2, tig = lane & 3;

    int rA0 = tid >> 2, kqA0 = (tid & 3) * 4;
    int rA1 = (tid + 256) >> 2, kqA1 = ((tid + 256) & 3) * 4;
    int kB0 = tid >> 5, nB0 = (tid & 31) * 4;
    int kB1 = (tid + 256) >> 5, nB1 = ((tid + 256) & 31) * 4;

    // ldmatrix lane coordinates for A fragments
    int lblk = lane >> 3;
    int lrowOff = ((lblk & 1) << 3) + (lane & 7);
    int lkOff = (lblk & 2) << 1;  // 0 or 4

    float4 ra0, ra1, rb0, rb1;
    auto loadT = [&](int t) {
        int k0 = t * 16;
        ra0 = *(const float4*)(arow(bm + rA0) + k0 + kqA0);
        ra1 = *(const float4*)(arow(bm + rA1) + k0 + kqA1);
        rb0 = *(const float4*)(B + (size_t)(k0 + kB0) * HH + bn + nB0);
        rb1 = *(const float4*)(B + (size_t)(k0 + kB1) * HH + bn + nB1);
    };
    auto storeT = [&](int buf) {
        uint4 u0 = {f2tf(ra0.x), f2tf(ra0.y), f2tf(ra0.z), f2tf(ra0.w)};
        uint4 u1 = {f2tf(ra1.x), f2tf(ra1.y), f2tf(ra1.z), f2tf(ra1.w)};
        uint4 v0 = {f2tf(rb0.x), f2tf(rb0.y), f2tf(rb0.z), f2tf(rb0.w)};
        uint4 v1 = {f2tf(rb1.x), f2tf(rb1.y), f2tf(rb1.z), f2tf(rb1.w)};
        *(uint4*)&sm.As[buf][rA0][kqA0] = u0;
        *(uint4*)&sm.As[buf][rA1][kqA1] = u1;
        *(uint4*)&sm.Bs[buf][kB0][nB0] = v0;
        *(uint4*)&sm.Bs[buf][kB1][nB1] = v1;
    };

    float acc[4][4][4];
#pragma unroll
    for (int i = 0; i < 4; i++)
#pragma unroll
        for (int j = 0; j < 4; j++)
#pragma unroll
            for (int q = 0; q < 4; q++) acc[i][j][q] = 0.f;

    int T = K / 16;
    loadT(0);
    storeT(0);
    __syncthreads();
    for (int t = 0; t < T; t++) {
        int buf = t & 1;
        if (t + 1 < T) loadT(t + 1);
#pragma unroll
        for (int kk = 0; kk < 16; kk += 8) {
            uint32_t a[4][4], b[4][2];
#pragma unroll
            for (int mt = 0; mt < 4; mt++) {
                int row = warpM * 64 + mt * 16 + lrowOff;
                ldsm_x4(a[mt], s2u(&sm.As[buf][row][kk + lkOff]));
            }
#pragma unroll
            for (int nt = 0; nt < 4; nt++) {
                int c0 = warpN * 32 + nt * 8;
                b[nt][0] = sm.Bs[buf][kk + tig][c0 + g];
                b[nt][1] = sm.Bs[buf][kk + tig + 4][c0 + g];
            }
#pragma unroll
            for (int mt = 0; mt < 4; mt++)
#pragma unroll
                for (int nt = 0; nt < 4; nt++) mma1688tf(acc[mt][nt], a[mt], b[nt]);
        }
        if (t + 1 < T) storeT((t + 1) & 1);
        __syncthreads();
    }

#pragma unroll
    for (int mt = 0; mt < 4; mt++) {
        int row0 = bm + warpM * 64 + mt * 16 + g;
#pragma unroll
        for (int nt = 0; nt < 4; nt++) {
            int col = bn + warpN * 32 + nt * 8 + tig * 2;
            float bb0 = bias ? bias[col] : 0.f;
            float bb1 = bias ? bias[col + 1] : 0.f;
            float v0 = acc[mt][nt][0] + bb0, v1 = acc[mt][nt][1] + bb1;
            float v2 = acc[mt][nt][2] + bb0, v3 = acc[mt][nt][3] + bb1;
            if (relu) {
                v0 = fmaxf(v0, 0.f); v1 = fmaxf(v1, 0.f);
                v2 = fmaxf(v2, 0.f); v3 = fmaxf(v3, 0.f);
            }
            float2 p0 = {v0, v1}, p1 = {v2, v3};
            *(float2*)(C + (size_t)row0 * HH + col) = p0;
            *(float2*)(C + (size_t)(row0 + 8) * HH + col) = p1;
        }
    }
}

__global__ __launch_bounds__(256) void k_gemm_tc(const float* Aext, size_t AOff,
                                                 const float* __restrict__ B,
                                                 const float* __restrict__ bias,
                                                 size_t COff, int K, int relu) {
    const float* Abase = Aext ? Aext : scr(AOff);
    gemm_core([&](int m) { return Abase + (size_t)m * K; },
              [&](int) { return B; }, bias, bias, COff, K, relu);
}

__global__ __launch_bounds__(256) void k_gemm_dualA(const float* A0, const float* A1,
                                                    const float* __restrict__ B,
                                                    size_t COff, int K) {
    gemm_core([&](int m) {
                  return m < NN ? A0 + (size_t)m * K : A1 + (size_t)(m - NN) * K;
              },
              [&](int) { return B; }, nullptr, nullptr, COff, K, 0);
}

__global__ __launch_bounds__(256) void k_gemm_sel(size_t AOff,
                                                  const float* __restrict__ B0,
                                                  const float* __restrict__ B1,
                                                  const float* bias0, const float* bias1,
                                                  size_t COff, int K, int relu) {
    const float* Abase = scr(AOff);
    gemm_core([&](int m) { return Abase + (size_t)m * K; },
              [&](int bm) { return bm >= NN ? B1 : B0; },
              bias0, bias1, COff, K, relu);
}

// Row l2-normalize (simple).
__global__ void k_l2norm(size_t XOff, size_t outOff) {
    const float* X = scr(XOff);
    float* out = scr(outOff);
    int row = blockIdx.x, t = threadIdx.x;
    float x = X[(size_t)row * HH + t];
    float s = x * x;
#pragma unroll
    for (int o = 16; o; o >>= 1) s += __shfl_xor_sync(0xffffffffu, s, o);
    __shared__ float red[8];
    if ((t & 31) == 0) red[t >> 5] = s;
    __syncthreads();
    float tot = 0.f;
#pragma unroll
    for (int i = 0; i < 8; i++) tot += red[i];
    float inv = 1.0f / fmaxf(sqrtf(tot), 1e-12f);
    out[(size_t)row * HH + t] = x * inv;
}

// Batched l2norm: rows [0,NN) -> PROJ; rows [NN,3NN) -> H1P/H2P + Z1/Z2 bf16
__global__ void k_l2norm3(size_t XOff) {
    const float* X = scr(XOff);
    int row = blockIdx.x, t = threadIdx.x;
    float x = X[(size_t)row * HH + t];
    float s = x * x;
#pragma unroll
    for (int o = 16; o; o >>= 1) s += __shfl_xor_sync(0xffffffffu, s, o);
    __shared__ float red[8];
    if ((t & 31) == 0) red[t >> 5] = s;
    __syncthreads();
    float tot = 0.f;
#pragma unroll
    for (int i = 0; i < 8; i++) tot += red[i];
    float inv = 1.0f / fmaxf(sqrtf(tot), 1e-12f);
    float y = x * inv;
    if (row < NN) {
        scr(O_PROJ)[(size_t)row * HH + t] = y;
    } else {
        size_t r2 = (size_t)(row - NN);
        scr(O_H1P)[r2 * HH + t] = y;
        ((__nv_bfloat16*)scr(O_Z1))[r2 * HH + t] = __float2bfloat16(y);
    }
}

// ---------------------------------------------------------------------------
// Fused exp-gram, cp.async double buffer + ldmatrix fragments.
// ---------------------------------------------------------------------------
__global__ __launch_bounds__(256) void k_gram(size_t AOff, size_t BOff,
                                              size_t rowOff, long long colOff,
                                              int symmetric) {
    int bx = blockIdx.x, by = blockIdx.y;
    if (symmetric && bx < by) return;
    const __nv_bfloat16* A = (const __nv_bfloat16*)scr(O_Z1) + AOff;
    const __nv_bfloat16* Bm = (const __nv_bfloat16*)scr(O_Z1) + BOff;
    float* rowSum = scr(rowOff);
    __shared__ __nv_bfloat16 As[2][128][40];
    __shared__ __nv_bfloat16 Bs[2][128][40];
    int tid = threadIdx.x;
    int wid = tid >> 5, lane = tid & 31;
    int warpM = wid >> 2, warpN = wid & 3;
    int g = lane >> 2, tig = lane & 3;
    const int rowBase = by * 128, colBase = bx * 128;

    int rL0 = tid >> 2, kL0 = (tid & 3) * 8;
    int rL1 = (tid + 256) >> 2, kL1 = ((tid + 256) & 3) * 8;

    auto prefetch = [&](int t, int buf) {
        int k0 = t * 32;
        cpasync16(s2u(&As[buf][rL0][kL0]), A + (size_t)(rowBase + rL0) * HH + k0 + kL0);
        cpasync16(s2u(&As[buf][rL1][kL1]), A + (size_t)(rowBase + rL1) * HH + k0 + kL1);
        cpasync16(s2u(&Bs[buf][rL0][kL0]), Bm + (size_t)(colBase + rL0) * HH + k0 + kL0);
        cpasync16(s2u(&Bs[buf][rL1][kL1]), Bm + (size_t)(colBase + rL1) * HH + k0 + kL1);
    };

    float acc[4][4][4];
#pragma unroll
    for (int a = 0; a < 4; a++)
#pragma unroll
        for (int b = 0; b < 4; b++)
#pragma unroll
            for (int q = 0; q < 4; q++) acc[a][b][q] = 0.f;

    const int T = HH / 32;  // 8
    prefetch(0, 0);
    CP_COMMIT();
    for (int t = 0; t < T; t++) {
        int buf = t & 1;
        if (t + 1 < T) prefetch(t + 1, (t + 1) & 1);
        CP_COMMIT();
        CP_WAIT1();
        __syncthreads();
        uint32_t asb = s2u(&As[buf][0][0]);
        uint32_t bsb = s2u(&Bs[buf][0][0]);
#pragma unroll
        for (int kk = 0; kk < 32; kk += 16) {
            uint32_t af[4][4], bf[4][2];
#pragma unroll
            for (int mt = 0; mt < 4; mt++) {
                int row = warpM * 64 + mt * 16 + (lane & 15);
                int col = kk + ((lane >> 4) << 3);
                ldsm_x4(af[mt], asb + (row * 40 + col) * 2);
            }
#pragma unroll
            for (int nt = 0; nt < 4; nt++) {
                int row = warpN * 32 + nt * 8 + (lane & 7);
                int col = kk + (((lane >> 3) & 1) << 3);
                ldsm_x2(bf[nt], bsb + (row * 40 + col) * 2);
            }
#pragma unroll
            for (int mt = 0; mt < 4; mt++)
#pragma unroll
                for (int nt = 0; nt < 4; nt++) mma16816v(acc[mt][nt], af[mt], bf[nt]);
        }
        __syncthreads();
    }

    float rs[4][2], cs[4][2];
#pragma unroll
    for (int i = 0; i < 4; i++) { rs[i][0] = rs[i][1] = 0.f; cs[i][0] = cs[i][1] = 0.f; }
#pragma unroll
    for (int mt = 0; mt < 4; mt++)
#pragma unroll
        for (int nt = 0; nt < 4; nt++) {
            float e0 = exp2f(acc[mt][nt][0] * EXPC);
            float e1 = exp2f(acc[mt][nt][1] * EXPC);
            float e2 = exp2f(acc[mt][nt][2] * EXPC);
            float e3 = exp2f(acc[mt][nt][3] * EXPC);
            rs[mt][0] += e0 + e1; rs[mt][1] += e2 + e3;
            cs[nt][0] += e0 + e2; cs[nt][1] += e1 + e3;
        }
#pragma unroll
    for (int mt = 0; mt < 4; mt++)
#pragma unroll
        for (int h = 0; h < 2; h++) {
            float v = rs[mt][h];
            v += __shfl_xor_sync(0xffffffffu, v, 1);
            v += __shfl_xor_sync(0xffffffffu, v, 2);
            if (tig == 0) {
                int r = rowBase + warpM * 64 + mt * 16 + g + h * 8;
                atomicAdd(&rowSum[r], v);
            }
        }
    bool wantCol = symmetric ? (bx != by) : (colOff >= 0);
    if (wantCol) {
        float* dst = symmetric ? rowSum : scr((size_t)colOff);
#pragma unroll
        for (int nt = 0; nt < 4; nt++)
#pragma unroll
            for (int h = 0; h < 2; h++) {
                float v = cs[nt][h];
                v += __shfl_xor_sync(0xffffffffu, v, 4);
                v += __shfl_xor_sync(0xffffffffu, v, 8);
                v += __shfl_xor_sync(0xffffffffu, v, 16);
                if (g == 0) {
                    int c = colBase + warpN * 32 + nt * 8 + tig * 2 + h;
                    atomicAdd(&dst[c], v);
                }
            }
    }
}

// sii[i] = dot(A_i, B_i) fp32
__global__ void k_sii(size_t AOff, size_t BOff, size_t sOff) {
    const float* A = scr(AOff);
    const float* B = scr(BOff);
    int w = threadIdx.x >> 5, lane = threadIdx.x & 31;
    int row = blockIdx.x * 8 + w;
    const float* a = A + (size_t)row * HH + lane * 8;
    const float* b = B + (size_t)row * HH + lane * 8;
    float4 a0 = *(const float4*)a, a1 = *(const float4*)(a + 4);
    float4 b0 = *(const float4*)b, b1 = *(const float4*)(b + 4);
    float s = a0.x * b0.x + a0.y * b0.y + a0.z * b0.z + a0.w * b0.w +
              a1.x * b1.x + a1.y * b1.y + a1.z * b1.z + a1.w * b1.w;
#pragma unroll
    for (int o = 16; o; o >>= 1) s += __shfl_xor_sync(0xffffffffu, s, o);
    if (lane == 0) scr(sOff)[row] = s;
}

__global__ void k_semi() {
    int i = blockIdx.x * blockDim.x + threadIdx.x;
    if (i >= NN) return;
    float dl = scr(O_SII)[i] * 2.0f;
    float l1 = logf(scr(O_R1)[i] + scr(O_BR)[i] - EDIAG) - dl;
    float l2 = logf(scr(O_R2)[i] + scr(O_BC)[i] - EDIAG) - dl;
    scr(O_LSEM)[i] = 0.5f * (l1 + l2);
}

__global__ void k_contrast(const int* __restrict__ nbi, const int* __restrict__ ngi) {
    const float* proj = scr(O_PROJ);
    const float* uemd = scr(O_UEMD);
    const float* vn = scr(O_VN);
    int w = threadIdx.x >> 5, lane = threadIdx.x & 31;
    int n = blockIdx.x * 8 + w;
    float p[8], v[8];
    {
        const float4* pp = (const float4*)(proj + (size_t)n * HH + lane * 8);
        ((float4*)p)[0] = pp[0]; ((float4*)p)[1] = pp[1];
        const float4* vv = (const float4*)(vn + (size_t)n * HH + lane * 8);
        ((float4*)v)[0] = vv[0]; ((float4*)v)[1] = vv[1];
    }
    float posd[SS];
    float negsum = 0.f;
#pragma unroll
    for (int s = 0; s < SS; s++) {
        int nb = nbi[n * SS + s];
        const float4* uu = (const float4*)(uemd + (size_t)nb * HH + lane * 8);
        float u[8]; ((float4*)u)[0] = uu[0]; ((float4*)u)[1] = uu[1];
        float d = 0.f;
#pragma unroll
        for (int k = 0; k < 8; k++) d += p[k] * u[k];
#pragma unroll
        for (int o = 16; o; o >>= 1) d += __shfl_xor_sync(0xffffffffu, d, o);
        posd[s] = d;
        int ng = ngi[n * SS + s];
        const float4* qq = (const float4*)(vn + (size_t)ng * HH + lane * 8);
        float q[8]; ((float4*)q)[0] = qq[0]; ((float4*)q)[1] = qq[1];
        float d2 = 0.f;
#pragma unroll
        for (int k = 0; k < 8; k++) d2 += v[k] * q[k];
#pragma unroll
        for (int o = 16; o; o >>= 1) d2 += __shfl_xor_sync(0xffffffffu, d2, o);
        negsum += exp2f(d2 * EXPC);
    }
    float ns = 0.f, ps = 0.f;
#pragma unroll
    for (int s = 0; s < SS; s++) {
        float pos = exp2f(posd[s] * EXPC);
        ns += logf(pos + negsum);
        ps += posd[s] * 2.0f;
    }
    if (lane == 0) scr(O_LG)[n] = ns - ps;
}

__global__ void k_reduce(float* __restrict__ out) {
    __shared__ float s1[1024], s2m[1024];
    int t = threadIdx.x;
    float a = 0.f, b = 0.f;
    for (int i = t; i < NN; i += 1024) { a += scr(O_LG)[i]; b += scr(O_LSEM)[i]; }
    s1[t] = a; s2m[t] = b;
    __syncthreads();
    for (int s = 512; s > 0; s >>= 1) {
        if (t < s) { s1[t] += s1[t + s]; s2m[t] += s2m[t + s]; }
        __syncthreads();
    }
    if (t == 0) {
        float gacl = s1[0] / ((float)NN * (float)SS);
        float sem = s2m[0] / (float)NN;
        out[0] = gacl + 0.6f * sem;
        out[1] = gacl;
        out[2] = sem;
    }
}

// Alignment-agnostic copy (dst = out + 3 is NOT 16B aligned).
__global__ void k_copy(size_t srcOff, float* __restrict__ dst, size_t n4) {
    size_t i = (size_t)blockIdx.x * blockDim.x + threadIdx.x;
    if (i < n4) {
        float4 v = ((const float4*)scr(srcOff))[i];
        float* d = dst + i * 4;
        d[0] = v.x; d[1] = v.y; d[2] = v.z; d[3] = v.w;
    }
}

// ---------------------------------------------------------------------------
// Host launch: two-stream fork-join (capture-legal: event edges only).
// ---------------------------------------------------------------------------
extern "C" void kernel_launch(void* const* d_in, const int* in_sizes, int n_in,
                              void* d_out, int out_size) {
    const float* adj1 = (const float*)d_in[0];
    const float* adj2 = (const float*)d_in[1];
    const float* x1 = (const float*)d_in[2];
    const float* x2 = (const float*)d_in[3];
    const int* nbi = (const int*)d_in[4];
    const int* ngi = (const int*)d_in[5];
    const float* W1 = (const float*)d_in[6];
    const float* b1 = (const float*)d_in[7];
    const float* W2 = (const float*)d_in[8];
    const float* b2 = (const float*)d_in[9];
    const float* tW1 = (const float*)d_in[10];
    const float* tb1 = (const float*)d_in[11];
    const float* tW2 = (const float*)d_in[12];
    const float* tb2 = (const float*)d_in[13];
    const float* pW0 = (const float*)d_in[14];
    const float* pB0 = (const float*)d_in[15];
    const float* pW1 = (const float*)d_in[16];
    const float* pB1 = (const float*)d_in[17];
    const float* pW2 = (const float*)d_in[18];
    const float* pB2 = (const float*)d_in[19];
    const float* sW0 = (const float*)d_in[20];
    const float* sB0 = (const float*)d_in[21];
    const float* sW1 = (const float*)d_in[22];
    const float* sB1 = (const float*)d_in[23];
    const float* sW2 = (const float*)d_in[24];
    const float* sB2 = (const float*)d_in[25];

    float* out = (float*)d_out;
    size_t h3_off = (size_t)out_size - NH;

    dim3 gemmGrid(2, NN / 128);
    dim3 gemmGrid2(2, 2 * NN / 128);
    dim3 gemmGrid3(2, 3 * NN / 128);
    dim3 gramGrid(128, 128);

    // side stream + events (created per call; kernel_launch only runs a few
    // times — graph replays do not execute this host code)
    cudaStream_t s2;
    cudaStreamCreateWithFlags(&s2, cudaStreamNonBlocking);
    cudaEvent_t evRoot, evD, evE2, evA2, evC, evM, evS;
    cudaEventCreateWithFlags(&evRoot, cudaEventDisableTiming);
    cudaEventCreateWithFlags(&evD, cudaEventDisableTiming);
    cudaEventCreateWithFlags(&evE2, cudaEventDisableTiming);
    cudaEventCreateWithFlags(&evA2, cudaEventDisableTiming);
    cudaEventCreateWithFlags(&evC, cudaEventDisableTiming);
    cudaEventCreateWithFlags(&evM, cudaEventDisableTiming);
    cudaEventCreateWithFlags(&evS, cudaEventDisableTiming);

    // fork
    k_zero4<<<NN / 256, 256>>>();
    cudaEventRecord(evRoot, 0);
    cudaStreamWaitEvent(s2, evRoot, 0);

    // s2: adjacency scans (HBM)  ||  main: stage-A GEMMs (tensor)
    k_extract<<<NN, 256, 0, s2>>>(adj1, O_COLS1, O_CNT1);
    k_extract<<<NN, 256, 0, s2>>>(adj2, O_COLS2, O_CNT2);
    cudaEventRecord(evE2, s2);

    k_gemm_dualA<<<gemmGrid2, 256>>>(x1, x2, W1, O_P1, DIN);
    cudaEventRecord(evD, 0);
    k_gemm_tc<<<gemmGrid, 256>>>(x1, 0, tW1, nullptr, O_T1, DIN, 0);

    // s2: spmm(H1,H2) needs extract1 (s2-ordered) + dualA (evD)
    cudaStreamWaitEvent(s2, evD, 0);
    k_spmm2<<<NN, 256, 0, s2>>>(O_COLS1, O_CNT1, O_P1, O_P2, b1, b1, O_H1, O_H2);
    cudaEventRecord(evA2, s2);

    // main: spmm(G3A,UA) needs extract2 (evE2) + dualA + T1 (stream-ordered)
    cudaStreamWaitEvent(0, evE2, 0);
    k_spmm2<<<NN, 256>>>(O_COLS2, O_CNT2, O_P1, O_T1, b1, tb1, O_G3A, O_UA);
    k_gemm_sel<<<gemmGrid2, 256>>>(O_G3A, W2, tW2, nullptr, nullptr, O_G3B, HH, 0);
    k_spmm2<<<NN, 256>>>(O_COLS2, O_CNT2, O_G3B, O_UB, b2, tb2, O_H3, O_U);
    cudaEventRecord(evC, 0);

    // s2: h3-copy + small l2norms overlap with main MLP GEMMs
    cudaStreamWaitEvent(s2, evC, 0);
    k_copy<<<(unsigned)((NH / 4 + 255) / 256), 256, 0, s2>>>(O_H3, out + h3_off, NH / 4);
    k_l2norm<<<NN, 256, 0, s2>>>(O_U, O_UEMD);
    k_l2norm<<<NN, 256, 0, s2>>>(O_H3, O_VN);

    // main: batched MLP on [h3; h1; h2] (needs spmm(H1,H2): evA2)
    cudaStreamWaitEvent(0, evA2, 0);
    k_gemm_sel<<<gemmGrid3, 256>>>(O_H3, pW0, sW0, pB0, sB0, O_PAIRA, HH, 1);
    k_gemm_sel<<<gemmGrid3, 256>>>(O_PAIRA, pW1, sW1, pB1, sB1, O_PAIRB, HH, 1);
    k_gemm_sel<<<gemmGrid3, 256>>>(O_PAIRB, pW2, sW2, pB2, sB2, O_PAIRA, HH, 0);
    k_l2norm3<<<3 * NN, 256>>>(O_PAIRA);
    cudaEventRecord(evM, 0);

    // s2: sii + contrast overlap with main grams
    cudaStreamWaitEvent(s2, evM, 0);
    k_sii<<<NN / 8, 256, 0, s2>>>(O_H1P, O_H2P, O_SII);
    k_contrast<<<NN / 8, 256, 0, s2>>>(nbi, ngi);
    cudaEventRecord(evS, s2);

    // main: fused exp-gram row/col sums
    k_gram<<<gramGrid, 256>>>(0, 0, O_R1, -1, 1);
    k_gram<<<gramGrid, 256>>>(NH, NH, O_R2, -1, 1);
    k_gram<<<gramGrid, 256>>>(0, NH, O_BR, (long long)O_BC, 0);

    // join + finalize
    cudaStreamWaitEvent(0, evS, 0);
    k_semi<<<NN / 256, 256>>>();
    k_reduce<<<1, 1024>>>(out);
}